// round 12
// baseline (speedup 1.0000x reference)
#include <cuda_runtime.h>
#include <cmath>

static constexpr int B_    = 256;
static constexpr int TR_   = 512;
static constexpr int H_    = 128;
static constexpr int TA_   = 64;
static constexpr int PSTD_ = 32;
static constexpr int PSTA_ = 16;
static constexpr int HH_   = 64;                 // head hidden
static constexpr int FD_   = H_ + PSTD_ + PSTA_; // 176

typedef unsigned long long ull;

// ---------------- packed-f32x2 helpers (dual-rate fp32 pipe) ----------------
__device__ __forceinline__ ull fma2_(ull a, ull b, ull c) {
    ull d;
    asm("fma.rn.f32x2 %0, %1, %2, %3;" : "=l"(d) : "l"(a), "l"(b), "l"(c));
    return d;
}
__device__ __forceinline__ float2 unpack2_(ull v) {
    unsigned l, h;
    asm("mov.b64 {%0, %1}, %2;" : "=r"(l), "=r"(h) : "l"(v));
    return make_float2(__uint_as_float(l), __uint_as_float(h));
}

// ---------------- scratch (device global: allocation-free) ----------------
//   xhat  : [131072,128]  @ 0
//   inp   : [131072,256]  @ 16777216
//   htil  : [131072,128]  @ 50331648
//   gi    : [131072,384]  @ 67108864
//   delta : [131072,128]  @ 117440512
__device__ float g_scratch[134217728];

__device__ __forceinline__ float sigmoidf_(float x) { return 1.f / (1.f + expf(-x)); }

// ---------------------------------------------------------------------------
// Phase 0: elementwise prep.  delta = 1/(1+e^dt) (== exp(-softplus(dt)))
// ---------------------------------------------------------------------------
__global__ __launch_bounds__(256) void prep_kernel(
    const float* __restrict__ X, const float* __restrict__ M,
    const float* __restrict__ DT, const float* __restrict__ xmean,
    float* __restrict__ delta, float* __restrict__ xhat, float* __restrict__ inp)
{
    int i4 = blockIdx.x * blockDim.x + threadIdx.x;   // float4 index
    const float4 x4 = reinterpret_cast<const float4*>(X)[i4];
    const float4 m4 = reinterpret_cast<const float4*>(M)[i4];
    const float4 t4 = reinterpret_cast<const float4*>(DT)[i4];
    int row = i4 >> 5;
    int c4  = i4 & 31;
    const float4 xm4 = reinterpret_cast<const float4*>(xmean)[c4];

    float4 d4, xh4, xd4;
#pragma unroll
    for (int c = 0; c < 4; c++) {
        float x  = ((const float*)&x4)[c];
        float m  = ((const float*)&m4)[c];
        float dt = ((const float*)&t4)[c];
        float xm = ((const float*)&xm4)[c];
        float d  = 1.f / (1.f + expf(dt));
        float xh = m * x + (1.f - m) * xm;
        float xd = m * x + (1.f - m) * (d * xh + (1.f - d) * xm);
        ((float*)&d4)[c]  = d;
        ((float*)&xh4)[c] = xh;
        ((float*)&xd4)[c] = xd;
    }
    reinterpret_cast<float4*>(delta)[i4] = d4;
    reinterpret_cast<float4*>(xhat)[i4]  = xh4;
    reinterpret_cast<float4*>(inp)[row * 64 + c4]      = xd4;  // x_dec
    reinterpret_cast<float4*>(inp)[row * 64 + 32 + c4] = m4;   // m
}

// ---------------------------------------------------------------------------
// Phase 1: C[M,N] = A[M,K] @ Bw[N,K]^T + bias ; EPI=1 -> tanh epilogue
// BM=BN=128, BK=16, 256 threads, 8x8 microtile, f32x2 packed over row-pairs.
// B stored in smem PRE-DUPLICATED in pairs, m-blocked with 20-word stride:
// one LDS.128 yields two ready f32x2 splats (no MOV splats in the hot loop).
// ---------------------------------------------------------------------------
template <int EPI>
__global__ __launch_bounds__(256, 2) void sgemm2(
    const float* __restrict__ A, const float* __restrict__ Bw,
    const float* __restrict__ bias, float* __restrict__ C,
    int M, int N, int K)
{
    constexpr int BK = 16;
    __shared__ float As[BK][128];
    __shared__ float Bs2[BK][16][20];   // [k][col-block m][8 dup pairs + 4 pad]

    const int bm = blockIdx.y * 128;
    const int bn = blockIdx.x * 128;
    const int tid = threadIdx.x;
    const int tr = (tid >> 4) << 3;       // 0..120
    const int tc = (tid & 15) << 3;       // 0..120
    const int lRow = tid >> 2;            // 0..63
    const int lCol = (tid & 3) << 2;      // 0,4,8,12
    const int mB = tc >> 3;               // my column block

    ull acc[4][8];                        // acc[i2][j]: rows (tr+2i2, tr+2i2+1)
#pragma unroll
    for (int i = 0; i < 4; i++)
#pragma unroll
        for (int j = 0; j < 8; j++) acc[i][j] = 0ull;

    const float* Aptr = A + (size_t)bm * K;
    const float* Bptr = Bw + (size_t)bn * K;

    for (int k0 = 0; k0 < K; k0 += BK) {
#pragma unroll
        for (int h = 0; h < 2; h++) {
            int r = lRow + h * 64;
            float4 va = *reinterpret_cast<const float4*>(Aptr + (size_t)r * K + k0 + lCol);
            As[lCol + 0][r] = va.x; As[lCol + 1][r] = va.y;
            As[lCol + 2][r] = va.z; As[lCol + 3][r] = va.w;
            float4 vb = *reinterpret_cast<const float4*>(Bptr + (size_t)r * K + k0 + lCol);
            int m = r >> 3, jj = (r & 7) << 1;
            *(float2*)&Bs2[lCol + 0][m][jj] = make_float2(vb.x, vb.x);
            *(float2*)&Bs2[lCol + 1][m][jj] = make_float2(vb.y, vb.y);
            *(float2*)&Bs2[lCol + 2][m][jj] = make_float2(vb.z, vb.z);
            *(float2*)&Bs2[lCol + 3][m][jj] = make_float2(vb.w, vb.w);
        }
        __syncthreads();
#pragma unroll
        for (int k = 0; k < BK; k++) {
            ulonglong2 aP0 = *reinterpret_cast<const ulonglong2*>(&As[k][tr]);
            ulonglong2 aP1 = *reinterpret_cast<const ulonglong2*>(&As[k][tr + 4]);
#pragma unroll
            for (int jp = 0; jp < 4; jp++) {
                // two splatted columns (tc+2jp, tc+2jp+1) in one LDS.128
                ulonglong2 bp = *reinterpret_cast<const ulonglong2*>(&Bs2[k][mB][4 * jp]);
                acc[0][2 * jp]     = fma2_(aP0.x, bp.x, acc[0][2 * jp]);
                acc[0][2 * jp + 1] = fma2_(aP0.x, bp.y, acc[0][2 * jp + 1]);
                acc[1][2 * jp]     = fma2_(aP0.y, bp.x, acc[1][2 * jp]);
                acc[1][2 * jp + 1] = fma2_(aP0.y, bp.y, acc[1][2 * jp + 1]);
                acc[2][2 * jp]     = fma2_(aP1.x, bp.x, acc[2][2 * jp]);
                acc[2][2 * jp + 1] = fma2_(aP1.x, bp.y, acc[2][2 * jp + 1]);
                acc[3][2 * jp]     = fma2_(aP1.y, bp.x, acc[3][2 * jp]);
                acc[3][2 * jp + 1] = fma2_(aP1.y, bp.y, acc[3][2 * jp + 1]);
            }
        }
        __syncthreads();
    }

    float bv[8];
    *(float4*)&bv[0] = *(const float4*)&bias[bn + tc];
    *(float4*)&bv[4] = *(const float4*)&bias[bn + tc + 4];
#pragma unroll
    for (int i2 = 0; i2 < 4; i2++) {
        float oL[8], oH[8];
#pragma unroll
        for (int j = 0; j < 8; j++) {
            float2 p = unpack2_(acc[i2][j]);
            float vl = p.x + bv[j];
            float vh = p.y + bv[j];
            oL[j] = EPI ? tanhf(vl) : vl;
            oH[j] = EPI ? tanhf(vh) : vh;
        }
        float* crowL = C + (size_t)(bm + tr + 2 * i2 + 0) * N + bn + tc;
        float* crowH = C + (size_t)(bm + tr + 2 * i2 + 1) * N + bn + tc;
        *(float4*)&crowL[0] = *(float4*)&oL[0];
        *(float4*)&crowL[4] = *(float4*)&oL[4];
        *(float4*)&crowH[0] = *(float4*)&oH[0];
        *(float4*)&crowH[4] = *(float4*)&oH[4];
    }
}

// ---------------------------------------------------------------------------
// Phase 2: GRU recurrence, f32x2 over k-pairs.
// 128 CTAs x 256 threads. Thread (j = tid&127, h = tid>>7) owns h[row h][j]
// and covers k in [64h, 64h+64): 20 W-pairs/gate in REGISTERS, 12 streamed
// from smem (per-thread-contiguous, 592B stride -> conflict-free LDS.128).
// All hp reads are LDS.128 broadcasts. Cross-half reduction via smem.
// ---------------------------------------------------------------------------
__global__ __launch_bounds__(256) void recurrence3(
    const float* __restrict__ gi, const float* __restrict__ delta,
    const float* __restrict__ htil, const float* __restrict__ Whh,
    const float* __restrict__ bhh, float* __restrict__ Hraw)
{
    extern __shared__ float sm[];
    // sW: per-j region [h][g][12 pairs] = 576B, padded stride 592B; 128 j's
    float* sWf = sm;                         // 75,776 B = 18,944 floats
    float* hpA = sm + 18944;                 // row0 h' [128]
    float* hpB = hpA + 128;                  // row1 h' [128]
    float* red = hpB + 128;                  // [2 rows][3 gates][128]

    const int tid = threadIdx.x;
    const int j = tid & 127;
    const int h = tid >> 7;

    // ---- fill streamed W: pairs i=0..11 <-> k = 64h + 40 + 2i ----
    for (int s = tid; s < 128 * 72; s += 256) {
        int jj = s / 72;
        int rem = s - jj * 72;
        int hh = rem / 36; rem -= hh * 36;
        int g  = rem / 12;
        int i  = rem - g * 12;
        ull v = *reinterpret_cast<const ull*>(
            &Whh[(size_t)(g * 128 + jj) * 128 + 64 * hh + 40 + 2 * i]);
        *reinterpret_cast<ull*>(
            reinterpret_cast<char*>(sWf) + jj * 592 + hh * 288 + g * 96 + i * 8) = v;
    }
    // ---- register-resident W: pairs i=0..19 <-> k = 64h + 2i ----
    ull wr[20], wz[20], wn[20];
#pragma unroll
    for (int i = 0; i < 20; i++) {
        int k = 64 * h + 2 * i;
        wr[i] = *reinterpret_cast<const ull*>(&Whh[(size_t)(j) * 128 + k]);
        wz[i] = *reinterpret_cast<const ull*>(&Whh[(size_t)(128 + j) * 128 + k]);
        wn[i] = *reinterpret_cast<const ull*>(&Whh[(size_t)(256 + j) * 128 + k]);
    }
    const float br = bhh[j], bz = bhh[128 + j], bn = bhh[256 + j];

    const size_t base = ((size_t)blockIdx.x * 2 + h) * TR_;  // my row's time base
    float hreg = 0.f;
    // prefetch t = 0 (my row only)
    float d  = delta[base * 128 + j];
    float ht = htil[base * 128 + j];
    float gr = gi[base * 384 + j];
    float gz = gi[base * 384 + 128 + j];
    float gn = gi[base * 384 + 256 + j];
    __syncthreads();

    const char* sWme = reinterpret_cast<const char*>(sWf) + j * 592 + h * 288;
    float* myHp = h ? hpB : hpA;
    float* redW = red + (1 - h) * 384;   // write other row's partials
    float* redR = red + h * 384;         // read my row's partials
    const int kb = 64 * h;

    for (int t = 0; t < TR_; t++) {
        const float cgr = gr, cgz = gz, cgn = gn;
        const float hp = d * hreg + (1.f - d) * ht;
        myHp[j] = hp;
        __syncthreads();

        // prefetch t+1 (clamped; last-iter values unused)
        {
            int tn = (t + 1 < TR_) ? t + 1 : t;
            size_t o = base + tn;
            d  = delta[o * 128 + j];
            ht = htil[o * 128 + j];
            gr = gi[o * 384 + j];
            gz = gi[o * 384 + 128 + j];
            gn = gi[o * 384 + 256 + j];
        }

        ull ar0 = 0, az0 = 0, an0 = 0, ar1 = 0, az1 = 0, an1 = 0;
#pragma unroll
        for (int i2 = 0; i2 < 10; i2++) {        // register-W pairs 2i2, 2i2+1
            ulonglong2 A0 = *reinterpret_cast<const ulonglong2*>(&hpA[kb + 4 * i2]);
            ulonglong2 A1 = *reinterpret_cast<const ulonglong2*>(&hpB[kb + 4 * i2]);
            ar0 = fma2_(A0.x, wr[2 * i2], ar0); ar0 = fma2_(A0.y, wr[2 * i2 + 1], ar0);
            az0 = fma2_(A0.x, wz[2 * i2], az0); az0 = fma2_(A0.y, wz[2 * i2 + 1], az0);
            an0 = fma2_(A0.x, wn[2 * i2], an0); an0 = fma2_(A0.y, wn[2 * i2 + 1], an0);
            ar1 = fma2_(A1.x, wr[2 * i2], ar1); ar1 = fma2_(A1.y, wr[2 * i2 + 1], ar1);
            az1 = fma2_(A1.x, wz[2 * i2], az1); az1 = fma2_(A1.y, wz[2 * i2 + 1], az1);
            an1 = fma2_(A1.x, wn[2 * i2], an1); an1 = fma2_(A1.y, wn[2 * i2 + 1], an1);
        }
#pragma unroll
        for (int l = 0; l < 6; l++) {            // streamed pairs 2l, 2l+1
            ulonglong2 A0 = *reinterpret_cast<const ulonglong2*>(&hpA[kb + 40 + 4 * l]);
            ulonglong2 A1 = *reinterpret_cast<const ulonglong2*>(&hpB[kb + 40 + 4 * l]);
            ulonglong2 WR = *reinterpret_cast<const ulonglong2*>(sWme + 0   + l * 16);
            ulonglong2 WZ = *reinterpret_cast<const ulonglong2*>(sWme + 96  + l * 16);
            ulonglong2 WN = *reinterpret_cast<const ulonglong2*>(sWme + 192 + l * 16);
            ar0 = fma2_(A0.x, WR.x, ar0); ar0 = fma2_(A0.y, WR.y, ar0);
            az0 = fma2_(A0.x, WZ.x, az0); az0 = fma2_(A0.y, WZ.y, az0);
            an0 = fma2_(A0.x, WN.x, an0); an0 = fma2_(A0.y, WN.y, an0);
            ar1 = fma2_(A1.x, WR.x, ar1); ar1 = fma2_(A1.y, WR.y, ar1);
            az1 = fma2_(A1.x, WZ.x, az1); az1 = fma2_(A1.y, WZ.y, az1);
            an1 = fma2_(A1.x, WN.x, an1); an1 = fma2_(A1.y, WN.y, an1);
        }
        // collapse even/odd lanes
        float2 p;
        p = unpack2_(ar0); float sR0 = p.x + p.y;
        p = unpack2_(az0); float sZ0 = p.x + p.y;
        p = unpack2_(an0); float sN0 = p.x + p.y;
        p = unpack2_(ar1); float sR1 = p.x + p.y;
        p = unpack2_(az1); float sZ1 = p.x + p.y;
        p = unpack2_(an1); float sN1 = p.x + p.y;

        float mR = h ? sR1 : sR0, mZ = h ? sZ1 : sZ0, mN = h ? sN1 : sN0;
        float oR = h ? sR0 : sR1, oZ = h ? sZ0 : sZ1, oN = h ? sN0 : sN1;
        redW[j] = oR; redW[128 + j] = oZ; redW[256 + j] = oN;
        __syncthreads();

        float ghr = mR + redR[j];
        float ghz = mZ + redR[128 + j];
        float ghn = mN + redR[256 + j];
        float r = sigmoidf_(cgr + ghr + br);
        float z = sigmoidf_(cgz + ghz + bz);
        float n = tanhf(cgn + r * (ghn + bn));
        hreg = (1.f - z) * n + z * hp;
        Hraw[(base + t) * 128 + j] = hreg;
    }
}

// ---------------------------------------------------------------------------
// Phase 3: gather + head MLP.  One warp per (b, ta); 8 warps/CTA share W1.
// ---------------------------------------------------------------------------
__global__ __launch_bounds__(256) void gather_head_kernel(
    const float* __restrict__ Hraw, const float* __restrict__ STD,
    const float* __restrict__ Z, const int* __restrict__ idx_map,
    const float* __restrict__ W1, const float* __restrict__ b1,
    const float* __restrict__ W2,
    float* __restrict__ eta, float* __restrict__ Hagg, float* __restrict__ maskO)
{
    extern __shared__ float sh[];
    float* W1s   = sh;                    // 64*176
    float* b1s   = W1s + HH_ * FD_;       // 64
    float* W2s   = b1s + HH_;             // 64
    float* feats = W2s + HH_;             // 8 * 184 (padded)

    const int tid = threadIdx.x;
    for (int s = tid; s < HH_ * FD_; s += 256) W1s[s] = W1[s];
    if (tid < HH_) { b1s[tid] = b1[tid]; W2s[tid] = W2[tid]; }
    __syncthreads();

    const int w = tid >> 5, lane = tid & 31;
    const int pair = blockIdx.x * 8 + w;      // 0 .. 16383
    const int b = pair >> 6, ta = pair & 63;

    const int idx = idx_map[b * TA_ + ta];
    const bool msk = idx >= 0;
    const int is = msk ? idx : 0;

    float* f = feats + w * 184;
    const float* hsrc = Hraw + ((size_t)b * TR_ + is) * H_;
    float4 hv = reinterpret_cast<const float4*>(hsrc)[lane];
    if (!msk) { hv.x = 0.f; hv.y = 0.f; hv.z = 0.f; hv.w = 0.f; }
    reinterpret_cast<float4*>(Hagg + ((size_t)b * TA_ + ta) * H_)[lane] = hv;
    reinterpret_cast<float4*>(f)[lane] = hv;
    f[128 + lane] = STD[(b * TA_ + ta) * PSTD_ + lane];
    if (lane < PSTA_) f[160 + lane] = Z[b * PSTA_ + lane];
    __syncwarp();

    float partial = 0.f;
#pragma unroll
    for (int jj0 = 0; jj0 < HH_; jj0 += 32) {
        int jj = jj0 + lane;
        float s = b1s[jj];
        const float* wrow = &W1s[jj * FD_];
#pragma unroll 8
        for (int k = 0; k < FD_; k++) s += f[k] * wrow[k];
        s = fmaxf(s, 0.f);
        partial += s * W2s[jj];
    }
#pragma unroll
    for (int o = 16; o; o >>= 1) partial += __shfl_xor_sync(0xffffffffu, partial, o);
    if (lane == 0) {
        eta[pair]   = partial;
        maskO[pair] = msk ? 1.f : 0.f;
    }
}

// ---------------------------------------------------------------------------
extern "C" void kernel_launch(void* const* d_in, const int* in_sizes, int n_in,
                              void* d_out, int out_size)
{
    const float* X     = (const float*)d_in[0];
    const float* M     = (const float*)d_in[1];
    const float* DT    = (const float*)d_in[2];
    const float* STD   = (const float*)d_in[3];
    const float* Z     = (const float*)d_in[4];
    const int*   idxm  = (const int*)  d_in[5];
    const float* xmean = (const float*)d_in[6];
    const float* Wd    = (const float*)d_in[7];
    const float* bd    = (const float*)d_in[8];
    const float* Wih   = (const float*)d_in[9];
    const float* bih   = (const float*)d_in[10];
    const float* Whh   = (const float*)d_in[11];
    const float* bhh   = (const float*)d_in[12];
    const float* W1    = (const float*)d_in[13];
    const float* b1    = (const float*)d_in[14];
    const float* W2    = (const float*)d_in[15];

    float* out   = (float*)d_out;
    float* eta   = out;                                    // 16384
    float* Hraw  = out + 16384;                            // 16,777,216
    float* Hagg  = out + 16384 + 16777216;                 // 2,097,152
    float* maskO = out + 16384 + 16777216 + 2097152;       // 16384

    float* scratch = nullptr;
    cudaGetSymbolAddress((void**)&scratch, g_scratch);
    float* xhat  = scratch;
    float* inp   = scratch + 16777216;
    float* htil  = scratch + 50331648;
    float* gi    = scratch + 67108864;
    float* delta = scratch + 117440512;

    // Phase 0
    prep_kernel<<<16384, 256>>>(X, M, DT, xmean, delta, xhat, inp);

    // Phase 1 (f32x2 packed GEMMs, pre-splatted B)
    sgemm2<1><<<dim3(1, 1024), 256>>>(xhat, Wd, bd, htil, 131072, 128, 128);
    sgemm2<0><<<dim3(3, 1024), 256>>>(inp, Wih, bih, gi, 131072, 384, 256);

    // Phase 2 (20 reg + 12 streamed W pairs, LDS.128 everywhere)
    const int rec_smem = 75776 + (128 + 128 + 768) * (int)sizeof(float); // 79,872 B
    cudaFuncSetAttribute(recurrence3,
                         cudaFuncAttributeMaxDynamicSharedMemorySize, rec_smem);
    recurrence3<<<128, 256, rec_smem>>>(gi, delta, htil, Whh, bhh, Hraw);

    // Phase 3
    const int gh_smem = (HH_ * FD_ + HH_ + HH_ + 8 * 184) * (int)sizeof(float); // 51,456 B
    cudaFuncSetAttribute(gather_head_kernel,
                         cudaFuncAttributeMaxDynamicSharedMemorySize, gh_smem);
    gather_head_kernel<<<2048, 256, gh_smem>>>(Hraw, STD, Z, idxm, W1, b1, W2,
                                               eta, Hagg, maskO);
}

// round 13
// speedup vs baseline: 1.0884x; 1.0884x over previous
#include <cuda_runtime.h>
#include <cmath>

static constexpr int B_    = 256;
static constexpr int TR_   = 512;
static constexpr int H_    = 128;
static constexpr int TA_   = 64;
static constexpr int PSTD_ = 32;
static constexpr int PSTA_ = 16;
static constexpr int HH_   = 64;                 // head hidden
static constexpr int FD_   = H_ + PSTD_ + PSTA_; // 176

typedef unsigned long long ull;

// ---------------- packed-f32x2 helpers (dual-rate fp32 pipe) ----------------
__device__ __forceinline__ ull fma2_(ull a, ull b, ull c) {
    ull d;
    asm("fma.rn.f32x2 %0, %1, %2, %3;" : "=l"(d) : "l"(a), "l"(b), "l"(c));
    return d;
}
__device__ __forceinline__ ull splat2_(float x) {
    unsigned u = __float_as_uint(x);
    ull r;
    asm("mov.b64 %0, {%1, %1};" : "=l"(r) : "r"(u));
    return r;
}
__device__ __forceinline__ float2 unpack2_(ull v) {
    unsigned l, h;
    asm("mov.b64 {%0, %1}, %2;" : "=r"(l), "=r"(h) : "l"(v));
    return make_float2(__uint_as_float(l), __uint_as_float(h));
}

// ---------------- scratch (device global: allocation-free) ----------------
//   xhat  : [131072,128]  @ 0
//   inp   : [131072,256]  @ 16777216
//   htil  : [131072,128]  @ 50331648
//   gi    : [131072,384]  @ 67108864
//   delta : [131072,128]  @ 117440512
__device__ float g_scratch[134217728];

__device__ __forceinline__ float sigmoidf_(float x) { return 1.f / (1.f + expf(-x)); }

// ---------------------------------------------------------------------------
// Phase 0: elementwise prep.  delta = 1/(1+e^dt) (== exp(-softplus(dt)))
// ---------------------------------------------------------------------------
__global__ __launch_bounds__(256) void prep_kernel(
    const float* __restrict__ X, const float* __restrict__ M,
    const float* __restrict__ DT, const float* __restrict__ xmean,
    float* __restrict__ delta, float* __restrict__ xhat, float* __restrict__ inp)
{
    int i4 = blockIdx.x * blockDim.x + threadIdx.x;   // float4 index
    const float4 x4 = reinterpret_cast<const float4*>(X)[i4];
    const float4 m4 = reinterpret_cast<const float4*>(M)[i4];
    const float4 t4 = reinterpret_cast<const float4*>(DT)[i4];
    int row = i4 >> 5;
    int c4  = i4 & 31;
    const float4 xm4 = reinterpret_cast<const float4*>(xmean)[c4];

    float4 d4, xh4, xd4;
#pragma unroll
    for (int c = 0; c < 4; c++) {
        float x  = ((const float*)&x4)[c];
        float m  = ((const float*)&m4)[c];
        float dt = ((const float*)&t4)[c];
        float xm = ((const float*)&xm4)[c];
        float d  = 1.f / (1.f + expf(dt));
        float xh = m * x + (1.f - m) * xm;
        float xd = m * x + (1.f - m) * (d * xh + (1.f - d) * xm);
        ((float*)&d4)[c]  = d;
        ((float*)&xh4)[c] = xh;
        ((float*)&xd4)[c] = xd;
    }
    reinterpret_cast<float4*>(delta)[i4] = d4;
    reinterpret_cast<float4*>(xhat)[i4]  = xh4;
    reinterpret_cast<float4*>(inp)[row * 64 + c4]      = xd4;  // x_dec
    reinterpret_cast<float4*>(inp)[row * 64 + 32 + c4] = m4;   // m
}

// ---------------------------------------------------------------------------
// Phase 1 (R11 version — measured best): C = A @ Bw^T + bias ; EPI=1 -> tanh.
// BM=BN=128, BK=16, 256 threads, 8x8 microtile, f32x2 packed over row-pairs.
// ---------------------------------------------------------------------------
template <int EPI>
__global__ __launch_bounds__(256, 2) void sgemm2(
    const float* __restrict__ A, const float* __restrict__ Bw,
    const float* __restrict__ bias, float* __restrict__ C,
    int M, int N, int K)
{
    constexpr int BK = 16;
    __shared__ float As[BK][128];
    __shared__ float Bs[BK][128];

    const int bm = blockIdx.y * 128;
    const int bn = blockIdx.x * 128;
    const int tid = threadIdx.x;
    const int tr = (tid >> 4) << 3;       // 0..120
    const int tc = (tid & 15) << 3;       // 0..120
    const int lRow = tid >> 2;            // 0..63
    const int lCol = (tid & 3) << 2;      // 0,4,8,12

    ull acc[4][8];                        // acc[i2][j] packs rows (tr+2*i2, tr+2*i2+1)
#pragma unroll
    for (int i = 0; i < 4; i++)
#pragma unroll
        for (int j = 0; j < 8; j++) acc[i][j] = 0ull;

    const float* Aptr = A + (size_t)bm * K;
    const float* Bptr = Bw + (size_t)bn * K;

    for (int k0 = 0; k0 < K; k0 += BK) {
#pragma unroll
        for (int h = 0; h < 2; h++) {
            int r = lRow + h * 64;
            float4 va = *reinterpret_cast<const float4*>(Aptr + (size_t)r * K + k0 + lCol);
            As[lCol + 0][r] = va.x; As[lCol + 1][r] = va.y;
            As[lCol + 2][r] = va.z; As[lCol + 3][r] = va.w;
            float4 vb = *reinterpret_cast<const float4*>(Bptr + (size_t)r * K + k0 + lCol);
            Bs[lCol + 0][r] = vb.x; Bs[lCol + 1][r] = vb.y;
            Bs[lCol + 2][r] = vb.z; Bs[lCol + 3][r] = vb.w;
        }
        __syncthreads();
#pragma unroll
        for (int k = 0; k < BK; k++) {
            ulonglong2 aP0 = *reinterpret_cast<const ulonglong2*>(&As[k][tr]);
            ulonglong2 aP1 = *reinterpret_cast<const ulonglong2*>(&As[k][tr + 4]);
            float4 b0 = *reinterpret_cast<const float4*>(&Bs[k][tc]);
            float4 b1 = *reinterpret_cast<const float4*>(&Bs[k][tc + 4]);
            ull bb[8];
            bb[0] = splat2_(b0.x); bb[1] = splat2_(b0.y);
            bb[2] = splat2_(b0.z); bb[3] = splat2_(b0.w);
            bb[4] = splat2_(b1.x); bb[5] = splat2_(b1.y);
            bb[6] = splat2_(b1.z); bb[7] = splat2_(b1.w);
#pragma unroll
            for (int j = 0; j < 8; j++) {
                acc[0][j] = fma2_(aP0.x, bb[j], acc[0][j]);
                acc[1][j] = fma2_(aP0.y, bb[j], acc[1][j]);
                acc[2][j] = fma2_(aP1.x, bb[j], acc[2][j]);
                acc[3][j] = fma2_(aP1.y, bb[j], acc[3][j]);
            }
        }
        __syncthreads();
    }

    float bv[8];
    *(float4*)&bv[0] = *(const float4*)&bias[bn + tc];
    *(float4*)&bv[4] = *(const float4*)&bias[bn + tc + 4];
#pragma unroll
    for (int i2 = 0; i2 < 4; i2++) {
        float oL[8], oH[8];
#pragma unroll
        for (int j = 0; j < 8; j++) {
            float2 p = unpack2_(acc[i2][j]);
            float vl = p.x + bv[j];
            float vh = p.y + bv[j];
            oL[j] = EPI ? tanhf(vl) : vl;
            oH[j] = EPI ? tanhf(vh) : vh;
        }
        float* crowL = C + (size_t)(bm + tr + 2 * i2 + 0) * N + bn + tc;
        float* crowH = C + (size_t)(bm + tr + 2 * i2 + 1) * N + bn + tc;
        *(float4*)&crowL[0] = *(float4*)&oL[0];
        *(float4*)&crowL[4] = *(float4*)&oL[4];
        *(float4*)&crowH[0] = *(float4*)&oH[0];
        *(float4*)&crowH[4] = *(float4*)&oH[4];
    }
}

// ---------------------------------------------------------------------------
// Phase 2: GRU recurrence, 512 threads (4 warps/SMSP for latency hiding).
// Thread (j = tid&127, q = tid>>7) computes BOTH batch rows over k-quarter
// [32q, 32q+32): 8 W-pairs/gate in registers, 8 streamed from smem
// (per-thread 208B-stride regions, region = q*128+j -> lane stride 52 words
// == 20 mod 32 -> conflict-free LDS.128). 4-way partial reduction via smem;
// threads q<2 own the per-row state (hreg, prefetch, gates, final update).
// ---------------------------------------------------------------------------
__global__ __launch_bounds__(512) void recurrence4(
    const float* __restrict__ gi, const float* __restrict__ delta,
    const float* __restrict__ htil, const float* __restrict__ Whh,
    const float* __restrict__ bhh, float* __restrict__ Hraw)
{
    extern __shared__ float sm[];
    char*  sWb = reinterpret_cast<char*>(sm);   // 512 regions x 208B = 106,496
    float* hp  = sm + 26624;                    // [2][128]
    float* red = hp + 256;                      // [4 q][2 r][3 g][128]

    const int tid = threadIdx.x;
    const int j = tid & 127;
    const int q = tid >> 7;

    // ---- fill streamed W: region (q*128+j): [g][i=0..7] ull, k = 32q+16+2i ----
    for (int s = tid; s < 512 * 24; s += 512) {
        int region = s / 24;
        int rem = s - region * 24;
        int g = rem >> 3, i = rem & 7;
        int jj = region & 127, qq = region >> 7;
        ull v = *reinterpret_cast<const ull*>(
            &Whh[(size_t)(g * 128 + jj) * 128 + 32 * qq + 16 + 2 * i]);
        *reinterpret_cast<ull*>(sWb + (size_t)region * 208 + g * 64 + i * 8) = v;
    }
    // ---- register W: pairs i=0..7, k = 32q + 2i ----
    ull wr[8], wz[8], wn[8];
#pragma unroll
    for (int i = 0; i < 8; i++) {
        int k = 32 * q + 2 * i;
        wr[i] = *reinterpret_cast<const ull*>(&Whh[(size_t)(j) * 128 + k]);
        wz[i] = *reinterpret_cast<const ull*>(&Whh[(size_t)(128 + j) * 128 + k]);
        wn[i] = *reinterpret_cast<const ull*>(&Whh[(size_t)(256 + j) * 128 + k]);
    }
    const float br = bhh[j], bz = bhh[128 + j], bn = bhh[256 + j];

    // per-row state lives in threads q<2 (row = q)
    const size_t base = ((size_t)blockIdx.x * 2 + (q & 1)) * TR_;
    float hreg = 0.f, d = 0.f, ht = 0.f, gr = 0.f, gz = 0.f, gn = 0.f;
    if (q < 2) {
        d  = delta[base * 128 + j];
        ht = htil[base * 128 + j];
        gr = gi[base * 384 + j];
        gz = gi[base * 384 + 128 + j];
        gn = gi[base * 384 + 256 + j];
    }
    __syncthreads();

    const char* sWme = sWb + (size_t)(q * 128 + j) * 208;
    const float* h0 = hp + 32 * q;
    const float* h1 = hp + 128 + 32 * q;

    for (int t = 0; t < TR_; t++) {
        const float cgr = gr, cgz = gz, cgn = gn;
        float hpv = 0.f;
        if (q < 2) {
            hpv = d * hreg + (1.f - d) * ht;
            hp[q * 128 + j] = hpv;
        }
        __syncthreads();

        if (q < 2) {   // prefetch t+1 (clamped; last-iter values unused)
            int tn = (t + 1 < TR_) ? t + 1 : t;
            size_t o = base + tn;
            d  = delta[o * 128 + j];
            ht = htil[o * 128 + j];
            gr = gi[o * 384 + j];
            gz = gi[o * 384 + 128 + j];
            gn = gi[o * 384 + 256 + j];
        }

        ull pr0 = 0, pz0 = 0, pn0 = 0, pr1 = 0, pz1 = 0, pn1 = 0;
#pragma unroll
        for (int i2 = 0; i2 < 4; i2++) {        // register pairs 2i2, 2i2+1
            ulonglong2 A0 = *reinterpret_cast<const ulonglong2*>(&h0[4 * i2]);
            ulonglong2 A1 = *reinterpret_cast<const ulonglong2*>(&h1[4 * i2]);
            pr0 = fma2_(A0.x, wr[2 * i2], pr0); pr0 = fma2_(A0.y, wr[2 * i2 + 1], pr0);
            pz0 = fma2_(A0.x, wz[2 * i2], pz0); pz0 = fma2_(A0.y, wz[2 * i2 + 1], pz0);
            pn0 = fma2_(A0.x, wn[2 * i2], pn0); pn0 = fma2_(A0.y, wn[2 * i2 + 1], pn0);
            pr1 = fma2_(A1.x, wr[2 * i2], pr1); pr1 = fma2_(A1.y, wr[2 * i2 + 1], pr1);
            pz1 = fma2_(A1.x, wz[2 * i2], pz1); pz1 = fma2_(A1.y, wz[2 * i2 + 1], pz1);
            pn1 = fma2_(A1.x, wn[2 * i2], pn1); pn1 = fma2_(A1.y, wn[2 * i2 + 1], pn1);
        }
#pragma unroll
        for (int l = 0; l < 4; l++) {            // streamed pairs 2l, 2l+1
            ulonglong2 A0 = *reinterpret_cast<const ulonglong2*>(&h0[16 + 4 * l]);
            ulonglong2 A1 = *reinterpret_cast<const ulonglong2*>(&h1[16 + 4 * l]);
            ulonglong2 WR = *reinterpret_cast<const ulonglong2*>(sWme + 0   + l * 16);
            ulonglong2 WZ = *reinterpret_cast<const ulonglong2*>(sWme + 64  + l * 16);
            ulonglong2 WN = *reinterpret_cast<const ulonglong2*>(sWme + 128 + l * 16);
            pr0 = fma2_(A0.x, WR.x, pr0); pr0 = fma2_(A0.y, WR.y, pr0);
            pz0 = fma2_(A0.x, WZ.x, pz0); pz0 = fma2_(A0.y, WZ.y, pz0);
            pn0 = fma2_(A0.x, WN.x, pn0); pn0 = fma2_(A0.y, WN.y, pn0);
            pr1 = fma2_(A1.x, WR.x, pr1); pr1 = fma2_(A1.y, WR.y, pr1);
            pz1 = fma2_(A1.x, WZ.x, pz1); pz1 = fma2_(A1.y, WZ.y, pz1);
            pn1 = fma2_(A1.x, WN.x, pn1); pn1 = fma2_(A1.y, WN.y, pn1);
        }
        // collapse even/odd lanes and publish 6 partials
        float2 p;
        p = unpack2_(pr0); red[((q * 2 + 0) * 3 + 0) * 128 + j] = p.x + p.y;
        p = unpack2_(pz0); red[((q * 2 + 0) * 3 + 1) * 128 + j] = p.x + p.y;
        p = unpack2_(pn0); red[((q * 2 + 0) * 3 + 2) * 128 + j] = p.x + p.y;
        p = unpack2_(pr1); red[((q * 2 + 1) * 3 + 0) * 128 + j] = p.x + p.y;
        p = unpack2_(pz1); red[((q * 2 + 1) * 3 + 1) * 128 + j] = p.x + p.y;
        p = unpack2_(pn1); red[((q * 2 + 1) * 3 + 2) * 128 + j] = p.x + p.y;
        __syncthreads();

        if (q < 2) {     // finalize row q
            float ghr = 0.f, ghz = 0.f, ghn = 0.f;
#pragma unroll
            for (int qq = 0; qq < 4; qq++) {
                ghr += red[((qq * 2 + q) * 3 + 0) * 128 + j];
                ghz += red[((qq * 2 + q) * 3 + 1) * 128 + j];
                ghn += red[((qq * 2 + q) * 3 + 2) * 128 + j];
            }
            float r = sigmoidf_(cgr + ghr + br);
            float z = sigmoidf_(cgz + ghz + bz);
            float n = tanhf(cgn + r * (ghn + bn));
            hreg = (1.f - z) * n + z * hpv;
            Hraw[(base + t) * 128 + j] = hreg;
        }
    }
}

// ---------------------------------------------------------------------------
// Phase 3: gather + head MLP.  One warp per (b, ta); 8 warps/CTA share W1.
// ---------------------------------------------------------------------------
__global__ __launch_bounds__(256) void gather_head_kernel(
    const float* __restrict__ Hraw, const float* __restrict__ STD,
    const float* __restrict__ Z, const int* __restrict__ idx_map,
    const float* __restrict__ W1, const float* __restrict__ b1,
    const float* __restrict__ W2,
    float* __restrict__ eta, float* __restrict__ Hagg, float* __restrict__ maskO)
{
    extern __shared__ float sh[];
    float* W1s   = sh;                    // 64*176
    float* b1s   = W1s + HH_ * FD_;       // 64
    float* W2s   = b1s + HH_;             // 64
    float* feats = W2s + HH_;             // 8 * 184 (padded)

    const int tid = threadIdx.x;
    for (int s = tid; s < HH_ * FD_; s += 256) W1s[s] = W1[s];
    if (tid < HH_) { b1s[tid] = b1[tid]; W2s[tid] = W2[tid]; }
    __syncthreads();

    const int w = tid >> 5, lane = tid & 31;
    const int pair = blockIdx.x * 8 + w;      // 0 .. 16383
    const int b = pair >> 6, ta = pair & 63;

    const int idx = idx_map[b * TA_ + ta];
    const bool msk = idx >= 0;
    const int is = msk ? idx : 0;

    float* f = feats + w * 184;
    const float* hsrc = Hraw + ((size_t)b * TR_ + is) * H_;
    float4 hv = reinterpret_cast<const float4*>(hsrc)[lane];
    if (!msk) { hv.x = 0.f; hv.y = 0.f; hv.z = 0.f; hv.w = 0.f; }
    reinterpret_cast<float4*>(Hagg + ((size_t)b * TA_ + ta) * H_)[lane] = hv;
    reinterpret_cast<float4*>(f)[lane] = hv;
    f[128 + lane] = STD[(b * TA_ + ta) * PSTD_ + lane];
    if (lane < PSTA_) f[160 + lane] = Z[b * PSTA_ + lane];
    __syncwarp();

    float partial = 0.f;
#pragma unroll
    for (int jj0 = 0; jj0 < HH_; jj0 += 32) {
        int jj = jj0 + lane;
        float s = b1s[jj];
        const float* wrow = &W1s[jj * FD_];
#pragma unroll 8
        for (int k = 0; k < FD_; k++) s += f[k] * wrow[k];
        s = fmaxf(s, 0.f);
        partial += s * W2s[jj];
    }
#pragma unroll
    for (int o = 16; o; o >>= 1) partial += __shfl_xor_sync(0xffffffffu, partial, o);
    if (lane == 0) {
        eta[pair]   = partial;
        maskO[pair] = msk ? 1.f : 0.f;
    }
}

// ---------------------------------------------------------------------------
extern "C" void kernel_launch(void* const* d_in, const int* in_sizes, int n_in,
                              void* d_out, int out_size)
{
    const float* X     = (const float*)d_in[0];
    const float* M     = (const float*)d_in[1];
    const float* DT    = (const float*)d_in[2];
    const float* STD   = (const float*)d_in[3];
    const float* Z     = (const float*)d_in[4];
    const int*   idxm  = (const int*)  d_in[5];
    const float* xmean = (const float*)d_in[6];
    const float* Wd    = (const float*)d_in[7];
    const float* bd    = (const float*)d_in[8];
    const float* Wih   = (const float*)d_in[9];
    const float* bih   = (const float*)d_in[10];
    const float* Whh   = (const float*)d_in[11];
    const float* bhh   = (const float*)d_in[12];
    const float* W1    = (const float*)d_in[13];
    const float* b1    = (const float*)d_in[14];
    const float* W2    = (const float*)d_in[15];

    float* out   = (float*)d_out;
    float* eta   = out;                                    // 16384
    float* Hraw  = out + 16384;                            // 16,777,216
    float* Hagg  = out + 16384 + 16777216;                 // 2,097,152
    float* maskO = out + 16384 + 16777216 + 2097152;       // 16384

    float* scratch = nullptr;
    cudaGetSymbolAddress((void**)&scratch, g_scratch);
    float* xhat  = scratch;
    float* inp   = scratch + 16777216;
    float* htil  = scratch + 50331648;
    float* gi    = scratch + 67108864;
    float* delta = scratch + 117440512;

    // Phase 0
    prep_kernel<<<16384, 256>>>(X, M, DT, xmean, delta, xhat, inp);

    // Phase 1 (R11 f32x2 GEMMs)
    sgemm2<1><<<dim3(1, 1024), 256>>>(xhat, Wd, bd, htil, 131072, 128, 128);
    sgemm2<0><<<dim3(3, 1024), 256>>>(inp, Wih, bih, gi, 131072, 384, 256);

    // Phase 2 (512-thread latency-hiding recurrence)
    const int rec_smem = 106496 + (256 + 3072) * (int)sizeof(float); // 119,808 B
    cudaFuncSetAttribute(recurrence4,
                         cudaFuncAttributeMaxDynamicSharedMemorySize, rec_smem);
    recurrence4<<<128, 512, rec_smem>>>(gi, delta, htil, Whh, bhh, Hraw);

    // Phase 3
    const int gh_smem = (HH_ * FD_ + HH_ + HH_ + 8 * 184) * (int)sizeof(float); // 51,456 B
    cudaFuncSetAttribute(gather_head_kernel,
                         cudaFuncAttributeMaxDynamicSharedMemorySize, gh_smem);
    gather_head_kernel<<<2048, 256, gh_smem>>>(Hraw, STD, Z, idxm, W1, b1, W2,
                                               eta, Hagg, maskO);
}

// round 14
// speedup vs baseline: 1.0886x; 1.0003x over previous
#include <cuda_runtime.h>
#include <cmath>

static constexpr int B_    = 256;
static constexpr int TR_   = 512;
static constexpr int H_    = 128;
static constexpr int TA_   = 64;
static constexpr int PSTD_ = 32;
static constexpr int PSTA_ = 16;
static constexpr int HH_   = 64;                 // head hidden
static constexpr int FD_   = H_ + PSTD_ + PSTA_; // 176

typedef unsigned long long ull;

// ---------------- packed-f32x2 helpers (dual-rate fp32 pipe) ----------------
__device__ __forceinline__ ull fma2_(ull a, ull b, ull c) {
    ull d;
    asm("fma.rn.f32x2 %0, %1, %2, %3;" : "=l"(d) : "l"(a), "l"(b), "l"(c));
    return d;
}
__device__ __forceinline__ ull splat2_(float x) {
    unsigned u = __float_as_uint(x);
    ull r;
    asm("mov.b64 %0, {%1, %1};" : "=l"(r) : "r"(u));
    return r;
}
__device__ __forceinline__ float2 unpack2_(ull v) {
    unsigned l, h;
    asm("mov.b64 {%0, %1}, %2;" : "=r"(l), "=r"(h) : "l"(v));
    return make_float2(__uint_as_float(l), __uint_as_float(h));
}

// ---------------- scratch (device global: allocation-free) ----------------
//   xhat  : [131072,128]  @ 0
//   inp   : [131072,256]  @ 16777216
//   htil  : [131072,128]  @ 50331648
//   gi    : [131072,384]  @ 67108864
//   delta : [131072,128]  @ 117440512
__device__ float g_scratch[134217728];

__device__ __forceinline__ float sigmoidf_(float x) { return 1.f / (1.f + expf(-x)); }

// ---------------------------------------------------------------------------
// Phase 0: elementwise prep.  delta = 1/(1+e^dt) (== exp(-softplus(dt)))
// ---------------------------------------------------------------------------
__global__ __launch_bounds__(256) void prep_kernel(
    const float* __restrict__ X, const float* __restrict__ M,
    const float* __restrict__ DT, const float* __restrict__ xmean,
    float* __restrict__ delta, float* __restrict__ xhat, float* __restrict__ inp)
{
    int i4 = blockIdx.x * blockDim.x + threadIdx.x;   // float4 index
    const float4 x4 = reinterpret_cast<const float4*>(X)[i4];
    const float4 m4 = reinterpret_cast<const float4*>(M)[i4];
    const float4 t4 = reinterpret_cast<const float4*>(DT)[i4];
    int row = i4 >> 5;
    int c4  = i4 & 31;
    const float4 xm4 = reinterpret_cast<const float4*>(xmean)[c4];

    float4 d4, xh4, xd4;
#pragma unroll
    for (int c = 0; c < 4; c++) {
        float x  = ((const float*)&x4)[c];
        float m  = ((const float*)&m4)[c];
        float dt = ((const float*)&t4)[c];
        float xm = ((const float*)&xm4)[c];
        float d  = 1.f / (1.f + expf(dt));
        float xh = m * x + (1.f - m) * xm;
        float xd = m * x + (1.f - m) * (d * xh + (1.f - d) * xm);
        ((float*)&d4)[c]  = d;
        ((float*)&xh4)[c] = xh;
        ((float*)&xd4)[c] = xd;
    }
    reinterpret_cast<float4*>(delta)[i4] = d4;
    reinterpret_cast<float4*>(xhat)[i4]  = xh4;
    reinterpret_cast<float4*>(inp)[row * 64 + c4]      = xd4;  // x_dec
    reinterpret_cast<float4*>(inp)[row * 64 + 32 + c4] = m4;   // m
}

// ---------------------------------------------------------------------------
// Phase 1 (R11 version — measured best): C = A @ Bw^T + bias ; EPI=1 -> tanh.
// BM=BN=128, BK=16, 256 threads, 8x8 microtile, f32x2 packed over row-pairs.
// ---------------------------------------------------------------------------
template <int EPI>
__global__ __launch_bounds__(256, 2) void sgemm2(
    const float* __restrict__ A, const float* __restrict__ Bw,
    const float* __restrict__ bias, float* __restrict__ C,
    int M, int N, int K)
{
    constexpr int BK = 16;
    __shared__ float As[BK][128];
    __shared__ float Bs[BK][128];

    const int bm = blockIdx.y * 128;
    const int bn = blockIdx.x * 128;
    const int tid = threadIdx.x;
    const int tr = (tid >> 4) << 3;       // 0..120
    const int tc = (tid & 15) << 3;       // 0..120
    const int lRow = tid >> 2;            // 0..63
    const int lCol = (tid & 3) << 2;      // 0,4,8,12

    ull acc[4][8];                        // acc[i2][j] packs rows (tr+2*i2, tr+2*i2+1)
#pragma unroll
    for (int i = 0; i < 4; i++)
#pragma unroll
        for (int j = 0; j < 8; j++) acc[i][j] = 0ull;

    const float* Aptr = A + (size_t)bm * K;
    const float* Bptr = Bw + (size_t)bn * K;

    for (int k0 = 0; k0 < K; k0 += BK) {
#pragma unroll
        for (int h = 0; h < 2; h++) {
            int r = lRow + h * 64;
            float4 va = *reinterpret_cast<const float4*>(Aptr + (size_t)r * K + k0 + lCol);
            As[lCol + 0][r] = va.x; As[lCol + 1][r] = va.y;
            As[lCol + 2][r] = va.z; As[lCol + 3][r] = va.w;
            float4 vb = *reinterpret_cast<const float4*>(Bptr + (size_t)r * K + k0 + lCol);
            Bs[lCol + 0][r] = vb.x; Bs[lCol + 1][r] = vb.y;
            Bs[lCol + 2][r] = vb.z; Bs[lCol + 3][r] = vb.w;
        }
        __syncthreads();
#pragma unroll
        for (int k = 0; k < BK; k++) {
            ulonglong2 aP0 = *reinterpret_cast<const ulonglong2*>(&As[k][tr]);
            ulonglong2 aP1 = *reinterpret_cast<const ulonglong2*>(&As[k][tr + 4]);
            float4 b0 = *reinterpret_cast<const float4*>(&Bs[k][tc]);
            float4 b1 = *reinterpret_cast<const float4*>(&Bs[k][tc + 4]);
            ull bb[8];
            bb[0] = splat2_(b0.x); bb[1] = splat2_(b0.y);
            bb[2] = splat2_(b0.z); bb[3] = splat2_(b0.w);
            bb[4] = splat2_(b1.x); bb[5] = splat2_(b1.y);
            bb[6] = splat2_(b1.z); bb[7] = splat2_(b1.w);
#pragma unroll
            for (int j = 0; j < 8; j++) {
                acc[0][j] = fma2_(aP0.x, bb[j], acc[0][j]);
                acc[1][j] = fma2_(aP0.y, bb[j], acc[1][j]);
                acc[2][j] = fma2_(aP1.x, bb[j], acc[2][j]);
                acc[3][j] = fma2_(aP1.y, bb[j], acc[3][j]);
            }
        }
        __syncthreads();
    }

    float bv[8];
    *(float4*)&bv[0] = *(const float4*)&bias[bn + tc];
    *(float4*)&bv[4] = *(const float4*)&bias[bn + tc + 4];
#pragma unroll
    for (int i2 = 0; i2 < 4; i2++) {
        float oL[8], oH[8];
#pragma unroll
        for (int j = 0; j < 8; j++) {
            float2 p = unpack2_(acc[i2][j]);
            float vl = p.x + bv[j];
            float vh = p.y + bv[j];
            oL[j] = EPI ? tanhf(vl) : vl;
            oH[j] = EPI ? tanhf(vh) : vh;
        }
        float* crowL = C + (size_t)(bm + tr + 2 * i2 + 0) * N + bn + tc;
        float* crowH = C + (size_t)(bm + tr + 2 * i2 + 1) * N + bn + tc;
        *(float4*)&crowL[0] = *(float4*)&oL[0];
        *(float4*)&crowL[4] = *(float4*)&oL[4];
        *(float4*)&crowH[0] = *(float4*)&oH[0];
        *(float4*)&crowH[4] = *(float4*)&oH[4];
    }
}

// ---------------------------------------------------------------------------
// Phase 2: GRU recurrence, 512 threads (4 warps/SMSP for latency hiding).
// Thread (j = tid&127, q = tid>>7) computes BOTH batch rows over k-quarter
// [32q, 32q+32): 8 W-pairs/gate in registers, 8 streamed from smem
// (per-thread 208B-stride regions, region = q*128+j -> lane stride 52 words
// == 20 mod 32 -> conflict-free LDS.128). 4-way partial reduction via smem;
// threads q<2 own the per-row state (hreg, prefetch, gates, final update).
// ---------------------------------------------------------------------------
__global__ __launch_bounds__(512) void recurrence4(
    const float* __restrict__ gi, const float* __restrict__ delta,
    const float* __restrict__ htil, const float* __restrict__ Whh,
    const float* __restrict__ bhh, float* __restrict__ Hraw)
{
    extern __shared__ float sm[];
    char*  sWb = reinterpret_cast<char*>(sm);   // 512 regions x 208B = 106,496
    float* hp  = sm + 26624;                    // [2][128]
    float* red = hp + 256;                      // [4 q][2 r][3 g][128]

    const int tid = threadIdx.x;
    const int j = tid & 127;
    const int q = tid >> 7;

    // ---- fill streamed W: region (q*128+j): [g][i=0..7] ull, k = 32q+16+2i ----
    for (int s = tid; s < 512 * 24; s += 512) {
        int region = s / 24;
        int rem = s - region * 24;
        int g = rem >> 3, i = rem & 7;
        int jj = region & 127, qq = region >> 7;
        ull v = *reinterpret_cast<const ull*>(
            &Whh[(size_t)(g * 128 + jj) * 128 + 32 * qq + 16 + 2 * i]);
        *reinterpret_cast<ull*>(sWb + (size_t)region * 208 + g * 64 + i * 8) = v;
    }
    // ---- register W: pairs i=0..7, k = 32q + 2i ----
    ull wr[8], wz[8], wn[8];
#pragma unroll
    for (int i = 0; i < 8; i++) {
        int k = 32 * q + 2 * i;
        wr[i] = *reinterpret_cast<const ull*>(&Whh[(size_t)(j) * 128 + k]);
        wz[i] = *reinterpret_cast<const ull*>(&Whh[(size_t)(128 + j) * 128 + k]);
        wn[i] = *reinterpret_cast<const ull*>(&Whh[(size_t)(256 + j) * 128 + k]);
    }
    const float br = bhh[j], bz = bhh[128 + j], bn = bhh[256 + j];

    // per-row state lives in threads q<2 (row = q)
    const size_t base = ((size_t)blockIdx.x * 2 + (q & 1)) * TR_;
    float hreg = 0.f, d = 0.f, ht = 0.f, gr = 0.f, gz = 0.f, gn = 0.f;
    if (q < 2) {
        d  = delta[base * 128 + j];
        ht = htil[base * 128 + j];
        gr = gi[base * 384 + j];
        gz = gi[base * 384 + 128 + j];
        gn = gi[base * 384 + 256 + j];
    }
    __syncthreads();

    const char* sWme = sWb + (size_t)(q * 128 + j) * 208;
    const float* h0 = hp + 32 * q;
    const float* h1 = hp + 128 + 32 * q;

    for (int t = 0; t < TR_; t++) {
        const float cgr = gr, cgz = gz, cgn = gn;
        float hpv = 0.f;
        if (q < 2) {
            hpv = d * hreg + (1.f - d) * ht;
            hp[q * 128 + j] = hpv;
        }
        __syncthreads();

        if (q < 2) {   // prefetch t+1 (clamped; last-iter values unused)
            int tn = (t + 1 < TR_) ? t + 1 : t;
            size_t o = base + tn;
            d  = delta[o * 128 + j];
            ht = htil[o * 128 + j];
            gr = gi[o * 384 + j];
            gz = gi[o * 384 + 128 + j];
            gn = gi[o * 384 + 256 + j];
        }

        ull pr0 = 0, pz0 = 0, pn0 = 0, pr1 = 0, pz1 = 0, pn1 = 0;
#pragma unroll
        for (int i2 = 0; i2 < 4; i2++) {        // register pairs 2i2, 2i2+1
            ulonglong2 A0 = *reinterpret_cast<const ulonglong2*>(&h0[4 * i2]);
            ulonglong2 A1 = *reinterpret_cast<const ulonglong2*>(&h1[4 * i2]);
            pr0 = fma2_(A0.x, wr[2 * i2], pr0); pr0 = fma2_(A0.y, wr[2 * i2 + 1], pr0);
            pz0 = fma2_(A0.x, wz[2 * i2], pz0); pz0 = fma2_(A0.y, wz[2 * i2 + 1], pz0);
            pn0 = fma2_(A0.x, wn[2 * i2], pn0); pn0 = fma2_(A0.y, wn[2 * i2 + 1], pn0);
            pr1 = fma2_(A1.x, wr[2 * i2], pr1); pr1 = fma2_(A1.y, wr[2 * i2 + 1], pr1);
            pz1 = fma2_(A1.x, wz[2 * i2], pz1); pz1 = fma2_(A1.y, wz[2 * i2 + 1], pz1);
            pn1 = fma2_(A1.x, wn[2 * i2], pn1); pn1 = fma2_(A1.y, wn[2 * i2 + 1], pn1);
        }
#pragma unroll
        for (int l = 0; l < 4; l++) {            // streamed pairs 2l, 2l+1
            ulonglong2 A0 = *reinterpret_cast<const ulonglong2*>(&h0[16 + 4 * l]);
            ulonglong2 A1 = *reinterpret_cast<const ulonglong2*>(&h1[16 + 4 * l]);
            ulonglong2 WR = *reinterpret_cast<const ulonglong2*>(sWme + 0   + l * 16);
            ulonglong2 WZ = *reinterpret_cast<const ulonglong2*>(sWme + 64  + l * 16);
            ulonglong2 WN = *reinterpret_cast<const ulonglong2*>(sWme + 128 + l * 16);
            pr0 = fma2_(A0.x, WR.x, pr0); pr0 = fma2_(A0.y, WR.y, pr0);
            pz0 = fma2_(A0.x, WZ.x, pz0); pz0 = fma2_(A0.y, WZ.y, pz0);
            pn0 = fma2_(A0.x, WN.x, pn0); pn0 = fma2_(A0.y, WN.y, pn0);
            pr1 = fma2_(A1.x, WR.x, pr1); pr1 = fma2_(A1.y, WR.y, pr1);
            pz1 = fma2_(A1.x, WZ.x, pz1); pz1 = fma2_(A1.y, WZ.y, pz1);
            pn1 = fma2_(A1.x, WN.x, pn1); pn1 = fma2_(A1.y, WN.y, pn1);
        }
        // collapse even/odd lanes and publish 6 partials
        float2 p;
        p = unpack2_(pr0); red[((q * 2 + 0) * 3 + 0) * 128 + j] = p.x + p.y;
        p = unpack2_(pz0); red[((q * 2 + 0) * 3 + 1) * 128 + j] = p.x + p.y;
        p = unpack2_(pn0); red[((q * 2 + 0) * 3 + 2) * 128 + j] = p.x + p.y;
        p = unpack2_(pr1); red[((q * 2 + 1) * 3 + 0) * 128 + j] = p.x + p.y;
        p = unpack2_(pz1); red[((q * 2 + 1) * 3 + 1) * 128 + j] = p.x + p.y;
        p = unpack2_(pn1); red[((q * 2 + 1) * 3 + 2) * 128 + j] = p.x + p.y;
        __syncthreads();

        if (q < 2) {     // finalize row q
            float ghr = 0.f, ghz = 0.f, ghn = 0.f;
#pragma unroll
            for (int qq = 0; qq < 4; qq++) {
                ghr += red[((qq * 2 + q) * 3 + 0) * 128 + j];
                ghz += red[((qq * 2 + q) * 3 + 1) * 128 + j];
                ghn += red[((qq * 2 + q) * 3 + 2) * 128 + j];
            }
            float r = sigmoidf_(cgr + ghr + br);
            float z = sigmoidf_(cgz + ghz + bz);
            float n = tanhf(cgn + r * (ghn + bn));
            hreg = (1.f - z) * n + z * hpv;
            Hraw[(base + t) * 128 + j] = hreg;
        }
    }
}

// ---------------------------------------------------------------------------
// Phase 3: gather + head MLP.  One warp per (b, ta); 8 warps/CTA share W1.
// ---------------------------------------------------------------------------
__global__ __launch_bounds__(256) void gather_head_kernel(
    const float* __restrict__ Hraw, const float* __restrict__ STD,
    const float* __restrict__ Z, const int* __restrict__ idx_map,
    const float* __restrict__ W1, const float* __restrict__ b1,
    const float* __restrict__ W2,
    float* __restrict__ eta, float* __restrict__ Hagg, float* __restrict__ maskO)
{
    extern __shared__ float sh[];
    float* W1s   = sh;                    // 64*176
    float* b1s   = W1s + HH_ * FD_;       // 64
    float* W2s   = b1s + HH_;             // 64
    float* feats = W2s + HH_;             // 8 * 184 (padded)

    const int tid = threadIdx.x;
    for (int s = tid; s < HH_ * FD_; s += 256) W1s[s] = W1[s];
    if (tid < HH_) { b1s[tid] = b1[tid]; W2s[tid] = W2[tid]; }
    __syncthreads();

    const int w = tid >> 5, lane = tid & 31;
    const int pair = blockIdx.x * 8 + w;      // 0 .. 16383
    const int b = pair >> 6, ta = pair & 63;

    const int idx = idx_map[b * TA_ + ta];
    const bool msk = idx >= 0;
    const int is = msk ? idx : 0;

    float* f = feats + w * 184;
    const float* hsrc = Hraw + ((size_t)b * TR_ + is) * H_;
    float4 hv = reinterpret_cast<const float4*>(hsrc)[lane];
    if (!msk) { hv.x = 0.f; hv.y = 0.f; hv.z = 0.f; hv.w = 0.f; }
    reinterpret_cast<float4*>(Hagg + ((size_t)b * TA_ + ta) * H_)[lane] = hv;
    reinterpret_cast<float4*>(f)[lane] = hv;
    f[128 + lane] = STD[(b * TA_ + ta) * PSTD_ + lane];
    if (lane < PSTA_) f[160 + lane] = Z[b * PSTA_ + lane];
    __syncwarp();

    float partial = 0.f;
#pragma unroll
    for (int jj0 = 0; jj0 < HH_; jj0 += 32) {
        int jj = jj0 + lane;
        float s = b1s[jj];
        const float* wrow = &W1s[jj * FD_];
#pragma unroll 8
        for (int k = 0; k < FD_; k++) s += f[k] * wrow[k];
        s = fmaxf(s, 0.f);
        partial += s * W2s[jj];
    }
#pragma unroll
    for (int o = 16; o; o >>= 1) partial += __shfl_xor_sync(0xffffffffu, partial, o);
    if (lane == 0) {
        eta[pair]   = partial;
        maskO[pair] = msk ? 1.f : 0.f;
    }
}

// ---------------------------------------------------------------------------
extern "C" void kernel_launch(void* const* d_in, const int* in_sizes, int n_in,
                              void* d_out, int out_size)
{
    const float* X     = (const float*)d_in[0];
    const float* M     = (const float*)d_in[1];
    const float* DT    = (const float*)d_in[2];
    const float* STD   = (const float*)d_in[3];
    const float* Z     = (const float*)d_in[4];
    const int*   idxm  = (const int*)  d_in[5];
    const float* xmean = (const float*)d_in[6];
    const float* Wd    = (const float*)d_in[7];
    const float* bd    = (const float*)d_in[8];
    const float* Wih   = (const float*)d_in[9];
    const float* bih   = (const float*)d_in[10];
    const float* Whh   = (const float*)d_in[11];
    const float* bhh   = (const float*)d_in[12];
    const float* W1    = (const float*)d_in[13];
    const float* b1    = (const float*)d_in[14];
    const float* W2    = (const float*)d_in[15];

    float* out   = (float*)d_out;
    float* eta   = out;                                    // 16384
    float* Hraw  = out + 16384;                            // 16,777,216
    float* Hagg  = out + 16384 + 16777216;                 // 2,097,152
    float* maskO = out + 16384 + 16777216 + 2097152;       // 16384

    float* scratch = nullptr;
    cudaGetSymbolAddress((void**)&scratch, g_scratch);
    float* xhat  = scratch;
    float* inp   = scratch + 16777216;
    float* htil  = scratch + 50331648;
    float* gi    = scratch + 67108864;
    float* delta = scratch + 117440512;

    // Phase 0
    prep_kernel<<<16384, 256>>>(X, M, DT, xmean, delta, xhat, inp);

    // Phase 1 (R11 f32x2 GEMMs)
    sgemm2<1><<<dim3(1, 1024), 256>>>(xhat, Wd, bd, htil, 131072, 128, 128);
    sgemm2<0><<<dim3(3, 1024), 256>>>(inp, Wih, bih, gi, 131072, 384, 256);

    // Phase 2 (512-thread latency-hiding recurrence)
    const int rec_smem = 106496 + (256 + 3072) * (int)sizeof(float); // 119,808 B
    cudaFuncSetAttribute(recurrence4,
                         cudaFuncAttributeMaxDynamicSharedMemorySize, rec_smem);
    recurrence4<<<128, 512, rec_smem>>>(gi, delta, htil, Whh, bhh, Hraw);

    // Phase 3
    const int gh_smem = (HH_ * FD_ + HH_ + HH_ + 8 * 184) * (int)sizeof(float); // 51,456 B
    cudaFuncSetAttribute(gather_head_kernel,
                         cudaFuncAttributeMaxDynamicSharedMemorySize, gh_smem);
    gather_head_kernel<<<2048, 256, gh_smem>>>(Hraw, STD, Z, idxm, W1, b1, W2,
                                               eta, Hagg, maskO);
}

// round 15
// speedup vs baseline: 1.1371x; 1.0445x over previous
#include <cuda_runtime.h>
#include <cmath>

static constexpr int B_    = 256;
static constexpr int TR_   = 512;
static constexpr int H_    = 128;
static constexpr int TA_   = 64;
static constexpr int PSTD_ = 32;
static constexpr int PSTA_ = 16;
static constexpr int HH_   = 64;                 // head hidden
static constexpr int FD_   = H_ + PSTD_ + PSTA_; // 176

typedef unsigned long long ull;

// ---------------- packed-f32x2 helpers (dual-rate fp32 pipe) ----------------
__device__ __forceinline__ ull fma2_(ull a, ull b, ull c) {
    ull d;
    asm("fma.rn.f32x2 %0, %1, %2, %3;" : "=l"(d) : "l"(a), "l"(b), "l"(c));
    return d;
}
__device__ __forceinline__ ull splat2_(float x) {
    unsigned u = __float_as_uint(x);
    ull r;
    asm("mov.b64 %0, {%1, %1};" : "=l"(r) : "r"(u));
    return r;
}
__device__ __forceinline__ float2 unpack2_(ull v) {
    unsigned l, h;
    asm("mov.b64 {%0, %1}, %2;" : "=r"(l), "=r"(h) : "l"(v));
    return make_float2(__uint_as_float(l), __uint_as_float(h));
}

// ---------------- scratch (device global: allocation-free) ----------------
//   xhat  : [131072,128]  @ 0
//   inp   : [131072,256]  @ 16777216
//   htil  : [131072,128]  @ 50331648
//   gi    : [131072,384]  @ 67108864
//   delta : [131072,128]  @ 117440512
__device__ float g_scratch[134217728];

__device__ __forceinline__ float sigmoidf_(float x) { return 1.f / (1.f + expf(-x)); }

// ---------------------------------------------------------------------------
// Phase 0: elementwise prep.  delta = 1/(1+e^dt) (== exp(-softplus(dt)))
// ---------------------------------------------------------------------------
__global__ __launch_bounds__(256) void prep_kernel(
    const float* __restrict__ X, const float* __restrict__ M,
    const float* __restrict__ DT, const float* __restrict__ xmean,
    float* __restrict__ delta, float* __restrict__ xhat, float* __restrict__ inp)
{
    int i4 = blockIdx.x * blockDim.x + threadIdx.x;   // float4 index
    const float4 x4 = reinterpret_cast<const float4*>(X)[i4];
    const float4 m4 = reinterpret_cast<const float4*>(M)[i4];
    const float4 t4 = reinterpret_cast<const float4*>(DT)[i4];
    int row = i4 >> 5;
    int c4  = i4 & 31;
    const float4 xm4 = reinterpret_cast<const float4*>(xmean)[c4];

    float4 d4, xh4, xd4;
#pragma unroll
    for (int c = 0; c < 4; c++) {
        float x  = ((const float*)&x4)[c];
        float m  = ((const float*)&m4)[c];
        float dt = ((const float*)&t4)[c];
        float xm = ((const float*)&xm4)[c];
        float d  = 1.f / (1.f + expf(dt));
        float xh = m * x + (1.f - m) * xm;
        float xd = m * x + (1.f - m) * (d * xh + (1.f - d) * xm);
        ((float*)&d4)[c]  = d;
        ((float*)&xh4)[c] = xh;
        ((float*)&xd4)[c] = xd;
    }
    reinterpret_cast<float4*>(delta)[i4] = d4;
    reinterpret_cast<float4*>(xhat)[i4]  = xh4;
    reinterpret_cast<float4*>(inp)[row * 64 + c4]      = xd4;  // x_dec
    reinterpret_cast<float4*>(inp)[row * 64 + 32 + c4] = m4;   // m
}

// ---------------------------------------------------------------------------
// Phase 1: C = A @ Bw^T + bias ; EPI=1 -> tanh.  BK=32 (half the barriers of
// the R11 version), BM=BN=128, 256 threads, 8x8 microtile, f32x2 row-pairs.
// ---------------------------------------------------------------------------
template <int EPI>
__global__ __launch_bounds__(256, 2) void sgemm3(
    const float* __restrict__ A, const float* __restrict__ Bw,
    const float* __restrict__ bias, float* __restrict__ C,
    int M, int N, int K)
{
    constexpr int BK = 32;
    __shared__ float As[BK][128];
    __shared__ float Bs[BK][128];

    const int bm = blockIdx.y * 128;
    const int bn = blockIdx.x * 128;
    const int tid = threadIdx.x;
    const int tr = (tid >> 4) << 3;       // 0..120
    const int tc = (tid & 15) << 3;       // 0..120
    const int lRow = tid >> 2;            // 0..63
    const int lCol4 = (tid & 3) << 2;     // 0,4,8,12

    ull acc[4][8];                        // acc[i2][j]: rows (tr+2i2, tr+2i2+1)
#pragma unroll
    for (int i = 0; i < 4; i++)
#pragma unroll
        for (int j = 0; j < 8; j++) acc[i][j] = 0ull;

    const float* Aptr = A + (size_t)bm * K;
    const float* Bptr = Bw + (size_t)bn * K;

    for (int k0 = 0; k0 < K; k0 += BK) {
#pragma unroll
        for (int h = 0; h < 2; h++) {
            int r = lRow + h * 64;
#pragma unroll
            for (int cc = 0; cc < 2; cc++) {
                int c = lCol4 + cc * 16;
                float4 va = *reinterpret_cast<const float4*>(Aptr + (size_t)r * K + k0 + c);
                As[c + 0][r] = va.x; As[c + 1][r] = va.y;
                As[c + 2][r] = va.z; As[c + 3][r] = va.w;
                float4 vb = *reinterpret_cast<const float4*>(Bptr + (size_t)r * K + k0 + c);
                Bs[c + 0][r] = vb.x; Bs[c + 1][r] = vb.y;
                Bs[c + 2][r] = vb.z; Bs[c + 3][r] = vb.w;
            }
        }
        __syncthreads();
#pragma unroll
        for (int k = 0; k < BK; k++) {
            ulonglong2 aP0 = *reinterpret_cast<const ulonglong2*>(&As[k][tr]);
            ulonglong2 aP1 = *reinterpret_cast<const ulonglong2*>(&As[k][tr + 4]);
            float4 b0 = *reinterpret_cast<const float4*>(&Bs[k][tc]);
            float4 b1 = *reinterpret_cast<const float4*>(&Bs[k][tc + 4]);
            ull bb[8];
            bb[0] = splat2_(b0.x); bb[1] = splat2_(b0.y);
            bb[2] = splat2_(b0.z); bb[3] = splat2_(b0.w);
            bb[4] = splat2_(b1.x); bb[5] = splat2_(b1.y);
            bb[6] = splat2_(b1.z); bb[7] = splat2_(b1.w);
#pragma unroll
            for (int j = 0; j < 8; j++) {
                acc[0][j] = fma2_(aP0.x, bb[j], acc[0][j]);
                acc[1][j] = fma2_(aP0.y, bb[j], acc[1][j]);
                acc[2][j] = fma2_(aP1.x, bb[j], acc[2][j]);
                acc[3][j] = fma2_(aP1.y, bb[j], acc[3][j]);
            }
        }
        __syncthreads();
    }

    float bv[8];
    *(float4*)&bv[0] = *(const float4*)&bias[bn + tc];
    *(float4*)&bv[4] = *(const float4*)&bias[bn + tc + 4];
#pragma unroll
    for (int i2 = 0; i2 < 4; i2++) {
        float oL[8], oH[8];
#pragma unroll
        for (int j = 0; j < 8; j++) {
            float2 p = unpack2_(acc[i2][j]);
            float vl = p.x + bv[j];
            float vh = p.y + bv[j];
            oL[j] = EPI ? tanhf(vl) : vl;
            oH[j] = EPI ? tanhf(vh) : vh;
        }
        float* crowL = C + (size_t)(bm + tr + 2 * i2 + 0) * N + bn + tc;
        float* crowH = C + (size_t)(bm + tr + 2 * i2 + 1) * N + bn + tc;
        *(float4*)&crowL[0] = *(float4*)&oL[0];
        *(float4*)&crowL[4] = *(float4*)&oL[4];
        *(float4*)&crowH[0] = *(float4*)&oH[0];
        *(float4*)&crowH[4] = *(float4*)&oH[4];
    }
}

// ---------------------------------------------------------------------------
// Phase 2: GRU recurrence, ONE barrier per step.
// 128 CTAs x 256 threads. Thread (j = tid>>1, e = tid&1) owns batch row e's
// h[j] and computes BOTH rows' partials over k-half [64e, 64e+64):
//   - 16 W-pairs/gate in registers, 16 streamed via conflict-free LDS.128
//     (layout [gate][ipair][tid] -> warp reads 512B contiguous)
//   - cross-half reduction = 3x __shfl_xor(1) (pair is the adjacent lane)
//   - hp double-buffered on t&1  ->  single __syncthreads per step
// ---------------------------------------------------------------------------
__global__ __launch_bounds__(256) void recurrence5(
    const float* __restrict__ gi, const float* __restrict__ delta,
    const float* __restrict__ htil, const float* __restrict__ Whh,
    const float* __restrict__ bhh, float* __restrict__ Hraw)
{
    extern __shared__ float sm[];
    ull*   Ws = reinterpret_cast<ull*>(sm);  // [3][8][256 tid][2] ull = 98304 B
    float* hp = sm + 24576;                  // [2 parity][2 rows][128]

    const int tid = threadIdx.x;
    const int j = tid >> 1;
    const int e = tid & 1;

    // ---- streamed W fill: s = ((g*8+ip)*256 + tt)*2 + w ; i = 2*ip + w,
    //      k = 64*ee + 32 + 2*i, (jj = tt>>1, ee = tt&1) ----
    for (int s = tid; s < 3 * 8 * 256 * 2; s += 256) {
        int w  = s & 1;
        int tt = (s >> 1) & 255;
        int gp = s >> 9;                 // 0..23
        int g  = gp >> 3, ip = gp & 7;
        int jj = tt >> 1, ee = tt & 1;
        Ws[s] = *reinterpret_cast<const ull*>(
            &Whh[(size_t)(g * 128 + jj) * 128 + 64 * ee + 32 + 4 * ip + 2 * w]);
    }
    // ---- register W: pairs i=0..15, k = 64e + 2i ----
    ull wr[16], wz[16], wn[16];
#pragma unroll
    for (int i = 0; i < 16; i++) {
        int k = 64 * e + 2 * i;
        wr[i] = *reinterpret_cast<const ull*>(&Whh[(size_t)(j) * 128 + k]);
        wz[i] = *reinterpret_cast<const ull*>(&Whh[(size_t)(128 + j) * 128 + k]);
        wn[i] = *reinterpret_cast<const ull*>(&Whh[(size_t)(256 + j) * 128 + k]);
    }
    const float br = bhh[j], bz = bhh[128 + j], bn = bhh[256 + j];

    const size_t base = ((size_t)blockIdx.x * 2 + e) * TR_;   // my row's time base
    float hreg = 0.f;
    // prefetch t = 0
    float d  = delta[base * 128 + j];
    float ht = htil[base * 128 + j];
    float gr = gi[base * 384 + j];
    float gz = gi[base * 384 + 128 + j];
    float gn = gi[base * 384 + 256 + j];
    __syncthreads();

    const ull* WsMe = Ws + 2 * tid;      // (g,ip) at offset (g*8+ip)*512
    const int kb = 64 * e;

    for (int t = 0; t < TR_; t++) {
        const float cgr = gr, cgz = gz, cgn = gn;
        float* hpc = hp + (t & 1) * 256;           // this step's buffer
        const float hpv = d * hreg + (1.f - d) * ht;
        hpc[e * 128 + j] = hpv;
        __syncthreads();                           // the ONLY barrier per step

        // prefetch t+1 (clamped; last-iter values unused)
        {
            int tn = (t + 1 < TR_) ? t + 1 : t;
            size_t o = base + tn;
            d  = delta[o * 128 + j];
            ht = htil[o * 128 + j];
            gr = gi[o * 384 + j];
            gz = gi[o * 384 + 128 + j];
            gn = gi[o * 384 + 256 + j];
        }

        const float* h0 = hpc + kb;          // row 0, my k-half
        const float* h1 = hpc + 128 + kb;    // row 1, my k-half

        ull pr0 = 0, pz0 = 0, pn0 = 0, pr1 = 0, pz1 = 0, pn1 = 0;
#pragma unroll
        for (int i2 = 0; i2 < 8; i2++) {     // register pairs 2i2, 2i2+1
            ulonglong2 A0 = *reinterpret_cast<const ulonglong2*>(&h0[4 * i2]);
            ulonglong2 A1 = *reinterpret_cast<const ulonglong2*>(&h1[4 * i2]);
            pr0 = fma2_(A0.x, wr[2 * i2], pr0); pr0 = fma2_(A0.y, wr[2 * i2 + 1], pr0);
            pz0 = fma2_(A0.x, wz[2 * i2], pz0); pz0 = fma2_(A0.y, wz[2 * i2 + 1], pz0);
            pn0 = fma2_(A0.x, wn[2 * i2], pn0); pn0 = fma2_(A0.y, wn[2 * i2 + 1], pn0);
            pr1 = fma2_(A1.x, wr[2 * i2], pr1); pr1 = fma2_(A1.y, wr[2 * i2 + 1], pr1);
            pz1 = fma2_(A1.x, wz[2 * i2], pz1); pz1 = fma2_(A1.y, wz[2 * i2 + 1], pz1);
            pn1 = fma2_(A1.x, wn[2 * i2], pn1); pn1 = fma2_(A1.y, wn[2 * i2 + 1], pn1);
        }
#pragma unroll
        for (int l = 0; l < 8; l++) {        // streamed pairs (k-local 32+4l .. 32+4l+3)
            ulonglong2 A0 = *reinterpret_cast<const ulonglong2*>(&h0[32 + 4 * l]);
            ulonglong2 A1 = *reinterpret_cast<const ulonglong2*>(&h1[32 + 4 * l]);
            ulonglong2 WR = *reinterpret_cast<const ulonglong2*>(&WsMe[(0 * 8 + l) * 512]);
            ulonglong2 WZ = *reinterpret_cast<const ulonglong2*>(&WsMe[(1 * 8 + l) * 512]);
            ulonglong2 WN = *reinterpret_cast<const ulonglong2*>(&WsMe[(2 * 8 + l) * 512]);
            pr0 = fma2_(A0.x, WR.x, pr0); pr0 = fma2_(A0.y, WR.y, pr0);
            pz0 = fma2_(A0.x, WZ.x, pz0); pz0 = fma2_(A0.y, WZ.y, pz0);
            pn0 = fma2_(A0.x, WN.x, pn0); pn0 = fma2_(A0.y, WN.y, pn0);
            pr1 = fma2_(A1.x, WR.x, pr1); pr1 = fma2_(A1.y, WR.y, pr1);
            pz1 = fma2_(A1.x, WZ.x, pz1); pz1 = fma2_(A1.y, WZ.y, pz1);
            pn1 = fma2_(A1.x, WN.x, pn1); pn1 = fma2_(A1.y, WN.y, pn1);
        }
        // collapse even/odd lanes
        float2 p;
        p = unpack2_(pr0); float sR0 = p.x + p.y;
        p = unpack2_(pz0); float sZ0 = p.x + p.y;
        p = unpack2_(pn0); float sN0 = p.x + p.y;
        p = unpack2_(pr1); float sR1 = p.x + p.y;
        p = unpack2_(pz1); float sZ1 = p.x + p.y;
        p = unpack2_(pn1); float sN1 = p.x + p.y;

        // keep my row's partial; swap the other row's partial with my pair lane
        float myR = e ? sR1 : sR0, myZ = e ? sZ1 : sZ0, myN = e ? sN1 : sN0;
        float otR = e ? sR0 : sR1, otZ = e ? sZ0 : sZ1, otN = e ? sN0 : sN1;
        float ghr = myR + __shfl_xor_sync(0xffffffffu, otR, 1);
        float ghz = myZ + __shfl_xor_sync(0xffffffffu, otZ, 1);
        float ghn = myN + __shfl_xor_sync(0xffffffffu, otN, 1);

        float r = sigmoidf_(cgr + ghr + br);
        float z = sigmoidf_(cgz + ghz + bz);
        float n = tanhf(cgn + r * (ghn + bn));
        hreg = (1.f - z) * n + z * hpv;
        Hraw[(base + t) * 128 + j] = hreg;
    }
}

// ---------------------------------------------------------------------------
// Phase 3: gather + head MLP.  One warp per (b, ta); 8 warps/CTA share W1.
// ---------------------------------------------------------------------------
__global__ __launch_bounds__(256) void gather_head_kernel(
    const float* __restrict__ Hraw, const float* __restrict__ STD,
    const float* __restrict__ Z, const int* __restrict__ idx_map,
    const float* __restrict__ W1, const float* __restrict__ b1,
    const float* __restrict__ W2,
    float* __restrict__ eta, float* __restrict__ Hagg, float* __restrict__ maskO)
{
    extern __shared__ float sh[];
    float* W1s   = sh;                    // 64*176
    float* b1s   = W1s + HH_ * FD_;       // 64
    float* W2s   = b1s + HH_;             // 64
    float* feats = W2s + HH_;             // 8 * 184 (padded)

    const int tid = threadIdx.x;
    for (int s = tid; s < HH_ * FD_; s += 256) W1s[s] = W1[s];
    if (tid < HH_) { b1s[tid] = b1[tid]; W2s[tid] = W2[tid]; }
    __syncthreads();

    const int w = tid >> 5, lane = tid & 31;
    const int pair = blockIdx.x * 8 + w;      // 0 .. 16383
    const int b = pair >> 6, ta = pair & 63;

    const int idx = idx_map[b * TA_ + ta];
    const bool msk = idx >= 0;
    const int is = msk ? idx : 0;

    float* f = feats + w * 184;
    const float* hsrc = Hraw + ((size_t)b * TR_ + is) * H_;
    float4 hv = reinterpret_cast<const float4*>(hsrc)[lane];
    if (!msk) { hv.x = 0.f; hv.y = 0.f; hv.z = 0.f; hv.w = 0.f; }
    reinterpret_cast<float4*>(Hagg + ((size_t)b * TA_ + ta) * H_)[lane] = hv;
    reinterpret_cast<float4*>(f)[lane] = hv;
    f[128 + lane] = STD[(b * TA_ + ta) * PSTD_ + lane];
    if (lane < PSTA_) f[160 + lane] = Z[b * PSTA_ + lane];
    __syncwarp();

    float partial = 0.f;
#pragma unroll
    for (int jj0 = 0; jj0 < HH_; jj0 += 32) {
        int jj = jj0 + lane;
        float s = b1s[jj];
        const float* wrow = &W1s[jj * FD_];
#pragma unroll 8
        for (int k = 0; k < FD_; k++) s += f[k] * wrow[k];
        s = fmaxf(s, 0.f);
        partial += s * W2s[jj];
    }
#pragma unroll
    for (int o = 16; o; o >>= 1) partial += __shfl_xor_sync(0xffffffffu, partial, o);
    if (lane == 0) {
        eta[pair]   = partial;
        maskO[pair] = msk ? 1.f : 0.f;
    }
}

// ---------------------------------------------------------------------------
extern "C" void kernel_launch(void* const* d_in, const int* in_sizes, int n_in,
                              void* d_out, int out_size)
{
    const float* X     = (const float*)d_in[0];
    const float* M     = (const float*)d_in[1];
    const float* DT    = (const float*)d_in[2];
    const float* STD   = (const float*)d_in[3];
    const float* Z     = (const float*)d_in[4];
    const int*   idxm  = (const int*)  d_in[5];
    const float* xmean = (const float*)d_in[6];
    const float* Wd    = (const float*)d_in[7];
    const float* bd    = (const float*)d_in[8];
    const float* Wih   = (const float*)d_in[9];
    const float* bih   = (const float*)d_in[10];
    const float* Whh   = (const float*)d_in[11];
    const float* bhh   = (const float*)d_in[12];
    const float* W1    = (const float*)d_in[13];
    const float* b1    = (const float*)d_in[14];
    const float* W2    = (const float*)d_in[15];

    float* out   = (float*)d_out;
    float* eta   = out;                                    // 16384
    float* Hraw  = out + 16384;                            // 16,777,216
    float* Hagg  = out + 16384 + 16777216;                 // 2,097,152
    float* maskO = out + 16384 + 16777216 + 2097152;       // 16384

    float* scratch = nullptr;
    cudaGetSymbolAddress((void**)&scratch, g_scratch);
    float* xhat  = scratch;
    float* inp   = scratch + 16777216;
    float* htil  = scratch + 50331648;
    float* gi    = scratch + 67108864;
    float* delta = scratch + 117440512;

    // Phase 0
    prep_kernel<<<16384, 256>>>(X, M, DT, xmean, delta, xhat, inp);

    // Phase 1 (BK=32 f32x2 GEMMs)
    sgemm3<1><<<dim3(1, 1024), 256>>>(xhat, Wd, bd, htil, 131072, 128, 128);
    sgemm3<0><<<dim3(3, 1024), 256>>>(inp, Wih, bih, gi, 131072, 384, 256);

    // Phase 2 (single-barrier, shuffle-reduced recurrence)
    const int rec_smem = 98304 + 512 * (int)sizeof(float);   // 100,352 B
    cudaFuncSetAttribute(recurrence5,
                         cudaFuncAttributeMaxDynamicSharedMemorySize, rec_smem);
    recurrence5<<<128, 256, rec_smem>>>(gi, delta, htil, Whh, bhh, Hraw);

    // Phase 3
    const int gh_smem = (HH_ * FD_ + HH_ + HH_ + 8 * 184) * (int)sizeof(float); // 51,456 B
    cudaFuncSetAttribute(gather_head_kernel,
                         cudaFuncAttributeMaxDynamicSharedMemorySize, gh_smem);
    gather_head_kernel<<<2048, 256, gh_smem>>>(Hraw, STD, Z, idxm, W1, b1, W2,
                                               eta, Hagg, maskO);
}

// round 16
// speedup vs baseline: 1.1377x; 1.0006x over previous
#include <cuda_runtime.h>
#include <cmath>

static constexpr int B_    = 256;
static constexpr int TR_   = 512;
static constexpr int H_    = 128;
static constexpr int TA_   = 64;
static constexpr int PSTD_ = 32;
static constexpr int PSTA_ = 16;
static constexpr int HH_   = 64;                 // head hidden
static constexpr int FD_   = H_ + PSTD_ + PSTA_; // 176

typedef unsigned long long ull;

// ---------------- packed-f32x2 helpers (dual-rate fp32 pipe) ----------------
__device__ __forceinline__ ull fma2_(ull a, ull b, ull c) {
    ull d;
    asm("fma.rn.f32x2 %0, %1, %2, %3;" : "=l"(d) : "l"(a), "l"(b), "l"(c));
    return d;
}
__device__ __forceinline__ ull splat2_(float x) {
    unsigned u = __float_as_uint(x);
    ull r;
    asm("mov.b64 %0, {%1, %1};" : "=l"(r) : "r"(u));
    return r;
}
__device__ __forceinline__ float2 unpack2_(ull v) {
    unsigned l, h;
    asm("mov.b64 {%0, %1}, %2;" : "=r"(l), "=r"(h) : "l"(v));
    return make_float2(__uint_as_float(l), __uint_as_float(h));
}

// ---------------- scratch (device global: allocation-free) ----------------
//   xhat  : [131072,128]  @ 0
//   inp   : [131072,256]  @ 16777216
//   htil  : [131072,128]  @ 50331648
//   gi    : [131072,384]  @ 67108864
//   delta : [131072,128]  @ 117440512
__device__ float g_scratch[134217728];

__device__ __forceinline__ float sigmoidf_(float x) { return 1.f / (1.f + expf(-x)); }

// ---------------------------------------------------------------------------
// Phase 0: elementwise prep.  delta = 1/(1+e^dt) (== exp(-softplus(dt)))
// ---------------------------------------------------------------------------
__global__ __launch_bounds__(256) void prep_kernel(
    const float* __restrict__ X, const float* __restrict__ M,
    const float* __restrict__ DT, const float* __restrict__ xmean,
    float* __restrict__ delta, float* __restrict__ xhat, float* __restrict__ inp)
{
    int i4 = blockIdx.x * blockDim.x + threadIdx.x;   // float4 index
    const float4 x4 = reinterpret_cast<const float4*>(X)[i4];
    const float4 m4 = reinterpret_cast<const float4*>(M)[i4];
    const float4 t4 = reinterpret_cast<const float4*>(DT)[i4];
    int row = i4 >> 5;
    int c4  = i4 & 31;
    const float4 xm4 = reinterpret_cast<const float4*>(xmean)[c4];

    float4 d4, xh4, xd4;
#pragma unroll
    for (int c = 0; c < 4; c++) {
        float x  = ((const float*)&x4)[c];
        float m  = ((const float*)&m4)[c];
        float dt = ((const float*)&t4)[c];
        float xm = ((const float*)&xm4)[c];
        float d  = 1.f / (1.f + expf(dt));
        float xh = m * x + (1.f - m) * xm;
        float xd = m * x + (1.f - m) * (d * xh + (1.f - d) * xm);
        ((float*)&d4)[c]  = d;
        ((float*)&xh4)[c] = xh;
        ((float*)&xd4)[c] = xd;
    }
    reinterpret_cast<float4*>(delta)[i4] = d4;
    reinterpret_cast<float4*>(xhat)[i4]  = xh4;
    reinterpret_cast<float4*>(inp)[row * 64 + c4]      = xd4;  // x_dec
    reinterpret_cast<float4*>(inp)[row * 64 + 32 + c4] = m4;   // m
}

// ---------------------------------------------------------------------------
// Phase 1: C = A @ Bw^T + bias ; EPI=1 -> tanh.  BK=32 (half the barriers of
// the R11 version), BM=BN=128, 256 threads, 8x8 microtile, f32x2 row-pairs.
// ---------------------------------------------------------------------------
template <int EPI>
__global__ __launch_bounds__(256, 2) void sgemm3(
    const float* __restrict__ A, const float* __restrict__ Bw,
    const float* __restrict__ bias, float* __restrict__ C,
    int M, int N, int K)
{
    constexpr int BK = 32;
    __shared__ float As[BK][128];
    __shared__ float Bs[BK][128];

    const int bm = blockIdx.y * 128;
    const int bn = blockIdx.x * 128;
    const int tid = threadIdx.x;
    const int tr = (tid >> 4) << 3;       // 0..120
    const int tc = (tid & 15) << 3;       // 0..120
    const int lRow = tid >> 2;            // 0..63
    const int lCol4 = (tid & 3) << 2;     // 0,4,8,12

    ull acc[4][8];                        // acc[i2][j]: rows (tr+2i2, tr+2i2+1)
#pragma unroll
    for (int i = 0; i < 4; i++)
#pragma unroll
        for (int j = 0; j < 8; j++) acc[i][j] = 0ull;

    const float* Aptr = A + (size_t)bm * K;
    const float* Bptr = Bw + (size_t)bn * K;

    for (int k0 = 0; k0 < K; k0 += BK) {
#pragma unroll
        for (int h = 0; h < 2; h++) {
            int r = lRow + h * 64;
#pragma unroll
            for (int cc = 0; cc < 2; cc++) {
                int c = lCol4 + cc * 16;
                float4 va = *reinterpret_cast<const float4*>(Aptr + (size_t)r * K + k0 + c);
                As[c + 0][r] = va.x; As[c + 1][r] = va.y;
                As[c + 2][r] = va.z; As[c + 3][r] = va.w;
                float4 vb = *reinterpret_cast<const float4*>(Bptr + (size_t)r * K + k0 + c);
                Bs[c + 0][r] = vb.x; Bs[c + 1][r] = vb.y;
                Bs[c + 2][r] = vb.z; Bs[c + 3][r] = vb.w;
            }
        }
        __syncthreads();
#pragma unroll
        for (int k = 0; k < BK; k++) {
            ulonglong2 aP0 = *reinterpret_cast<const ulonglong2*>(&As[k][tr]);
            ulonglong2 aP1 = *reinterpret_cast<const ulonglong2*>(&As[k][tr + 4]);
            float4 b0 = *reinterpret_cast<const float4*>(&Bs[k][tc]);
            float4 b1 = *reinterpret_cast<const float4*>(&Bs[k][tc + 4]);
            ull bb[8];
            bb[0] = splat2_(b0.x); bb[1] = splat2_(b0.y);
            bb[2] = splat2_(b0.z); bb[3] = splat2_(b0.w);
            bb[4] = splat2_(b1.x); bb[5] = splat2_(b1.y);
            bb[6] = splat2_(b1.z); bb[7] = splat2_(b1.w);
#pragma unroll
            for (int j = 0; j < 8; j++) {
                acc[0][j] = fma2_(aP0.x, bb[j], acc[0][j]);
                acc[1][j] = fma2_(aP0.y, bb[j], acc[1][j]);
                acc[2][j] = fma2_(aP1.x, bb[j], acc[2][j]);
                acc[3][j] = fma2_(aP1.y, bb[j], acc[3][j]);
            }
        }
        __syncthreads();
    }

    float bv[8];
    *(float4*)&bv[0] = *(const float4*)&bias[bn + tc];
    *(float4*)&bv[4] = *(const float4*)&bias[bn + tc + 4];
#pragma unroll
    for (int i2 = 0; i2 < 4; i2++) {
        float oL[8], oH[8];
#pragma unroll
        for (int j = 0; j < 8; j++) {
            float2 p = unpack2_(acc[i2][j]);
            float vl = p.x + bv[j];
            float vh = p.y + bv[j];
            oL[j] = EPI ? tanhf(vl) : vl;
            oH[j] = EPI ? tanhf(vh) : vh;
        }
        float* crowL = C + (size_t)(bm + tr + 2 * i2 + 0) * N + bn + tc;
        float* crowH = C + (size_t)(bm + tr + 2 * i2 + 1) * N + bn + tc;
        *(float4*)&crowL[0] = *(float4*)&oL[0];
        *(float4*)&crowL[4] = *(float4*)&oL[4];
        *(float4*)&crowH[0] = *(float4*)&oH[0];
        *(float4*)&crowH[4] = *(float4*)&oH[4];
    }
}

// ---------------------------------------------------------------------------
// Phase 2: GRU recurrence, ONE barrier per step.
// 128 CTAs x 256 threads. Thread (j = tid>>1, e = tid&1) owns batch row e's
// h[j] and computes BOTH rows' partials over k-half [64e, 64e+64):
//   - 16 W-pairs/gate in registers, 16 streamed via conflict-free LDS.128
//     (layout [gate][ipair][tid] -> warp reads 512B contiguous)
//   - cross-half reduction = 3x __shfl_xor(1) (pair is the adjacent lane)
//   - hp double-buffered on t&1  ->  single __syncthreads per step
// ---------------------------------------------------------------------------
__global__ __launch_bounds__(256) void recurrence5(
    const float* __restrict__ gi, const float* __restrict__ delta,
    const float* __restrict__ htil, const float* __restrict__ Whh,
    const float* __restrict__ bhh, float* __restrict__ Hraw)
{
    extern __shared__ float sm[];
    ull*   Ws = reinterpret_cast<ull*>(sm);  // [3][8][256 tid][2] ull = 98304 B
    float* hp = sm + 24576;                  // [2 parity][2 rows][128]

    const int tid = threadIdx.x;
    const int j = tid >> 1;
    const int e = tid & 1;

    // ---- streamed W fill: s = ((g*8+ip)*256 + tt)*2 + w ; i = 2*ip + w,
    //      k = 64*ee + 32 + 2*i, (jj = tt>>1, ee = tt&1) ----
    for (int s = tid; s < 3 * 8 * 256 * 2; s += 256) {
        int w  = s & 1;
        int tt = (s >> 1) & 255;
        int gp = s >> 9;                 // 0..23
        int g  = gp >> 3, ip = gp & 7;
        int jj = tt >> 1, ee = tt & 1;
        Ws[s] = *reinterpret_cast<const ull*>(
            &Whh[(size_t)(g * 128 + jj) * 128 + 64 * ee + 32 + 4 * ip + 2 * w]);
    }
    // ---- register W: pairs i=0..15, k = 64e + 2i ----
    ull wr[16], wz[16], wn[16];
#pragma unroll
    for (int i = 0; i < 16; i++) {
        int k = 64 * e + 2 * i;
        wr[i] = *reinterpret_cast<const ull*>(&Whh[(size_t)(j) * 128 + k]);
        wz[i] = *reinterpret_cast<const ull*>(&Whh[(size_t)(128 + j) * 128 + k]);
        wn[i] = *reinterpret_cast<const ull*>(&Whh[(size_t)(256 + j) * 128 + k]);
    }
    const float br = bhh[j], bz = bhh[128 + j], bn = bhh[256 + j];

    const size_t base = ((size_t)blockIdx.x * 2 + e) * TR_;   // my row's time base
    float hreg = 0.f;
    // prefetch t = 0
    float d  = delta[base * 128 + j];
    float ht = htil[base * 128 + j];
    float gr = gi[base * 384 + j];
    float gz = gi[base * 384 + 128 + j];
    float gn = gi[base * 384 + 256 + j];
    __syncthreads();

    const ull* WsMe = Ws + 2 * tid;      // (g,ip) at offset (g*8+ip)*512
    const int kb = 64 * e;

    for (int t = 0; t < TR_; t++) {
        const float cgr = gr, cgz = gz, cgn = gn;
        float* hpc = hp + (t & 1) * 256;           // this step's buffer
        const float hpv = d * hreg + (1.f - d) * ht;
        hpc[e * 128 + j] = hpv;
        __syncthreads();                           // the ONLY barrier per step

        // prefetch t+1 (clamped; last-iter values unused)
        {
            int tn = (t + 1 < TR_) ? t + 1 : t;
            size_t o = base + tn;
            d  = delta[o * 128 + j];
            ht = htil[o * 128 + j];
            gr = gi[o * 384 + j];
            gz = gi[o * 384 + 128 + j];
            gn = gi[o * 384 + 256 + j];
        }

        const float* h0 = hpc + kb;          // row 0, my k-half
        const float* h1 = hpc + 128 + kb;    // row 1, my k-half

        ull pr0 = 0, pz0 = 0, pn0 = 0, pr1 = 0, pz1 = 0, pn1 = 0;
#pragma unroll
        for (int i2 = 0; i2 < 8; i2++) {     // register pairs 2i2, 2i2+1
            ulonglong2 A0 = *reinterpret_cast<const ulonglong2*>(&h0[4 * i2]);
            ulonglong2 A1 = *reinterpret_cast<const ulonglong2*>(&h1[4 * i2]);
            pr0 = fma2_(A0.x, wr[2 * i2], pr0); pr0 = fma2_(A0.y, wr[2 * i2 + 1], pr0);
            pz0 = fma2_(A0.x, wz[2 * i2], pz0); pz0 = fma2_(A0.y, wz[2 * i2 + 1], pz0);
            pn0 = fma2_(A0.x, wn[2 * i2], pn0); pn0 = fma2_(A0.y, wn[2 * i2 + 1], pn0);
            pr1 = fma2_(A1.x, wr[2 * i2], pr1); pr1 = fma2_(A1.y, wr[2 * i2 + 1], pr1);
            pz1 = fma2_(A1.x, wz[2 * i2], pz1); pz1 = fma2_(A1.y, wz[2 * i2 + 1], pz1);
            pn1 = fma2_(A1.x, wn[2 * i2], pn1); pn1 = fma2_(A1.y, wn[2 * i2 + 1], pn1);
        }
#pragma unroll
        for (int l = 0; l < 8; l++) {        // streamed pairs (k-local 32+4l .. 32+4l+3)
            ulonglong2 A0 = *reinterpret_cast<const ulonglong2*>(&h0[32 + 4 * l]);
            ulonglong2 A1 = *reinterpret_cast<const ulonglong2*>(&h1[32 + 4 * l]);
            ulonglong2 WR = *reinterpret_cast<const ulonglong2*>(&WsMe[(0 * 8 + l) * 512]);
            ulonglong2 WZ = *reinterpret_cast<const ulonglong2*>(&WsMe[(1 * 8 + l) * 512]);
            ulonglong2 WN = *reinterpret_cast<const ulonglong2*>(&WsMe[(2 * 8 + l) * 512]);
            pr0 = fma2_(A0.x, WR.x, pr0); pr0 = fma2_(A0.y, WR.y, pr0);
            pz0 = fma2_(A0.x, WZ.x, pz0); pz0 = fma2_(A0.y, WZ.y, pz0);
            pn0 = fma2_(A0.x, WN.x, pn0); pn0 = fma2_(A0.y, WN.y, pn0);
            pr1 = fma2_(A1.x, WR.x, pr1); pr1 = fma2_(A1.y, WR.y, pr1);
            pz1 = fma2_(A1.x, WZ.x, pz1); pz1 = fma2_(A1.y, WZ.y, pz1);
            pn1 = fma2_(A1.x, WN.x, pn1); pn1 = fma2_(A1.y, WN.y, pn1);
        }
        // collapse even/odd lanes
        float2 p;
        p = unpack2_(pr0); float sR0 = p.x + p.y;
        p = unpack2_(pz0); float sZ0 = p.x + p.y;
        p = unpack2_(pn0); float sN0 = p.x + p.y;
        p = unpack2_(pr1); float sR1 = p.x + p.y;
        p = unpack2_(pz1); float sZ1 = p.x + p.y;
        p = unpack2_(pn1); float sN1 = p.x + p.y;

        // keep my row's partial; swap the other row's partial with my pair lane
        float myR = e ? sR1 : sR0, myZ = e ? sZ1 : sZ0, myN = e ? sN1 : sN0;
        float otR = e ? sR0 : sR1, otZ = e ? sZ0 : sZ1, otN = e ? sN0 : sN1;
        float ghr = myR + __shfl_xor_sync(0xffffffffu, otR, 1);
        float ghz = myZ + __shfl_xor_sync(0xffffffffu, otZ, 1);
        float ghn = myN + __shfl_xor_sync(0xffffffffu, otN, 1);

        float r = sigmoidf_(cgr + ghr + br);
        float z = sigmoidf_(cgz + ghz + bz);
        float n = tanhf(cgn + r * (ghn + bn));
        hreg = (1.f - z) * n + z * hpv;
        Hraw[(base + t) * 128 + j] = hreg;
    }
}

// ---------------------------------------------------------------------------
// Phase 3: gather + head MLP.  One warp per (b, ta); 8 warps/CTA share W1.
// ---------------------------------------------------------------------------
__global__ __launch_bounds__(256) void gather_head_kernel(
    const float* __restrict__ Hraw, const float* __restrict__ STD,
    const float* __restrict__ Z, const int* __restrict__ idx_map,
    const float* __restrict__ W1, const float* __restrict__ b1,
    const float* __restrict__ W2,
    float* __restrict__ eta, float* __restrict__ Hagg, float* __restrict__ maskO)
{
    extern __shared__ float sh[];
    float* W1s   = sh;                    // 64*176
    float* b1s   = W1s + HH_ * FD_;       // 64
    float* W2s   = b1s + HH_;             // 64
    float* feats = W2s + HH_;             // 8 * 184 (padded)

    const int tid = threadIdx.x;
    for (int s = tid; s < HH_ * FD_; s += 256) W1s[s] = W1[s];
    if (tid < HH_) { b1s[tid] = b1[tid]; W2s[tid] = W2[tid]; }
    __syncthreads();

    const int w = tid >> 5, lane = tid & 31;
    const int pair = blockIdx.x * 8 + w;      // 0 .. 16383
    const int b = pair >> 6, ta = pair & 63;

    const int idx = idx_map[b * TA_ + ta];
    const bool msk = idx >= 0;
    const int is = msk ? idx : 0;

    float* f = feats + w * 184;
    const float* hsrc = Hraw + ((size_t)b * TR_ + is) * H_;
    float4 hv = reinterpret_cast<const float4*>(hsrc)[lane];
    if (!msk) { hv.x = 0.f; hv.y = 0.f; hv.z = 0.f; hv.w = 0.f; }
    reinterpret_cast<float4*>(Hagg + ((size_t)b * TA_ + ta) * H_)[lane] = hv;
    reinterpret_cast<float4*>(f)[lane] = hv;
    f[128 + lane] = STD[(b * TA_ + ta) * PSTD_ + lane];
    if (lane < PSTA_) f[160 + lane] = Z[b * PSTA_ + lane];
    __syncwarp();

    float partial = 0.f;
#pragma unroll
    for (int jj0 = 0; jj0 < HH_; jj0 += 32) {
        int jj = jj0 + lane;
        float s = b1s[jj];
        const float* wrow = &W1s[jj * FD_];
#pragma unroll 8
        for (int k = 0; k < FD_; k++) s += f[k] * wrow[k];
        s = fmaxf(s, 0.f);
        partial += s * W2s[jj];
    }
#pragma unroll
    for (int o = 16; o; o >>= 1) partial += __shfl_xor_sync(0xffffffffu, partial, o);
    if (lane == 0) {
        eta[pair]   = partial;
        maskO[pair] = msk ? 1.f : 0.f;
    }
}

// ---------------------------------------------------------------------------
extern "C" void kernel_launch(void* const* d_in, const int* in_sizes, int n_in,
                              void* d_out, int out_size)
{
    const float* X     = (const float*)d_in[0];
    const float* M     = (const float*)d_in[1];
    const float* DT    = (const float*)d_in[2];
    const float* STD   = (const float*)d_in[3];
    const float* Z     = (const float*)d_in[4];
    const int*   idxm  = (const int*)  d_in[5];
    const float* xmean = (const float*)d_in[6];
    const float* Wd    = (const float*)d_in[7];
    const float* bd    = (const float*)d_in[8];
    const float* Wih   = (const float*)d_in[9];
    const float* bih   = (const float*)d_in[10];
    const float* Whh   = (const float*)d_in[11];
    const float* bhh   = (const float*)d_in[12];
    const float* W1    = (const float*)d_in[13];
    const float* b1    = (const float*)d_in[14];
    const float* W2    = (const float*)d_in[15];

    float* out   = (float*)d_out;
    float* eta   = out;                                    // 16384
    float* Hraw  = out + 16384;                            // 16,777,216
    float* Hagg  = out + 16384 + 16777216;                 // 2,097,152
    float* maskO = out + 16384 + 16777216 + 2097152;       // 16384

    float* scratch = nullptr;
    cudaGetSymbolAddress((void**)&scratch, g_scratch);
    float* xhat  = scratch;
    float* inp   = scratch + 16777216;
    float* htil  = scratch + 50331648;
    float* gi    = scratch + 67108864;
    float* delta = scratch + 117440512;

    // Phase 0
    prep_kernel<<<16384, 256>>>(X, M, DT, xmean, delta, xhat, inp);

    // Phase 1 (BK=32 f32x2 GEMMs)
    sgemm3<1><<<dim3(1, 1024), 256>>>(xhat, Wd, bd, htil, 131072, 128, 128);
    sgemm3<0><<<dim3(3, 1024), 256>>>(inp, Wih, bih, gi, 131072, 384, 256);

    // Phase 2 (single-barrier, shuffle-reduced recurrence)
    const int rec_smem = 98304 + 512 * (int)sizeof(float);   // 100,352 B
    cudaFuncSetAttribute(recurrence5,
                         cudaFuncAttributeMaxDynamicSharedMemorySize, rec_smem);
    recurrence5<<<128, 256, rec_smem>>>(gi, delta, htil, Whh, bhh, Hraw);

    // Phase 3
    const int gh_smem = (HH_ * FD_ + HH_ + HH_ + 8 * 184) * (int)sizeof(float); // 51,456 B
    cudaFuncSetAttribute(gather_head_kernel,
                         cudaFuncAttributeMaxDynamicSharedMemorySize, gh_smem);
    gather_head_kernel<<<2048, 256, gh_smem>>>(Hraw, STD, Z, idxm, W1, b1, W2,
                                               eta, Hagg, maskO);
}